// round 1
// baseline (speedup 1.0000x reference)
#include <cuda_runtime.h>
#include <math.h>

#define NN 2048
#define EE 65536
#define HH 8
#define CC 128
#define NEG 0.2f

#define BM 128
#define BN 128
#define BK 8

// ---------------- device scratch (static: no allocations allowed) ----------------
__device__ float g_A [NN*NN];
__device__ float g_A2[NN*NN];
__device__ float g_R [NN*NN];
__device__ float g_xh[NN*HH*CC];
__device__ float g_si[NN*HH];
__device__ float g_sj[NN*HH];
__device__ float g_z [HH*EE];
__device__ float g_mv[EE];
__device__ float g_hmax[HH];
__device__ float g_Zs[HH];
__device__ float g_norm[NN];
__device__ int   g_cnt[NN];
__device__ int   g_cur[NN];
__device__ int   g_off[NN+1];
__device__ int   g_ssrc[EE];
__device__ int   g_seid[EE];
__device__ float g_h1[NN*CC];
__device__ float g_h2[NN*CC];
__device__ float g_xskip[NN*CC];
__device__ int   g_is64;

// edge index load that works for int32 or int64 buffers
__device__ __forceinline__ int eidx(const void* ei, int pos) {
    if (g_is64) return (int)((const long long*)ei)[pos];
    return ((const int*)ei)[pos];
}

// ---------------- dtype detection ----------------
// If edge_index is int64 (values < 2048, nonneg), every odd 32-bit word is 0.
// If int32, odd words are real indices (almost surely nonzero somewhere).
__global__ void k_detect(const unsigned* __restrict__ w) {
    __shared__ int anynz;
    if (threadIdx.x == 0) anynz = 0;
    __syncthreads();
    unsigned v = 0;
    for (int i = 1 + 2 * threadIdx.x; i < 8192; i += 2 * blockDim.x) v |= w[i];
    if (v) anynz = 1;
    __syncthreads();
    if (threadIdx.x == 0) g_is64 = anynz ? 0 : 1;
}

// ---------------- adjacency build ----------------
__global__ void k_zeroA() {
    int i = blockIdx.x * blockDim.x + threadIdx.x;          // NN*NN/4 float4s
    ((float4*)g_A)[i] = make_float4(0.f, 0.f, 0.f, 0.f);
}

__global__ void k_buildA(const void* __restrict__ ei) {
    int e = blockIdx.x * blockDim.x + threadIdx.x;
    if (e >= EE) return;
    int s = eidx(ei, e), d = eidx(ei, EE + e);
    atomicAdd(&g_A[s * NN + d], 1.0f);
}

__global__ void k_diag() {
    int i = blockIdx.x * blockDim.x + threadIdx.x;
    if (i < NN) g_A[i * NN + i] += 1.0f;
}

// ---------------- fp32 SIMT GEMM: C = A*B (BT=false) or C = A*B^T (BT=true) ----------------
// MODE 0: C = acc ; MODE 1: C += acc ; MODE 2: C = acc + bias[n]
template<bool BT, int MODE>
__global__ __launch_bounds__(256, 2)
void gemm_f32(const float* __restrict__ A, const float* __restrict__ B,
              float* __restrict__ C, const float* __restrict__ bias,
              int M, int N, int K)
{
    __shared__ float As[BK][BM];
    __shared__ float Bs[BK][BN];
    const int tid = threadIdx.x;
    const int bm = blockIdx.y * BM;
    const int bn = blockIdx.x * BN;
    const int tx = tid & 15;          // 16 cols of 8
    const int ty = tid >> 4;          // 16 rows of 8

    const int aRow = tid >> 1;
    const int aCol = (tid & 1) * 4;

    float acc[8][8];
    #pragma unroll
    for (int i = 0; i < 8; i++)
        #pragma unroll
        for (int j = 0; j < 8; j++) acc[i][j] = 0.f;

    for (int k0 = 0; k0 < K; k0 += BK) {
        // load A tile (BM x BK), transpose into As[k][m]
        float4 av = *(const float4*)&A[(size_t)(bm + aRow) * K + k0 + aCol];
        As[aCol + 0][aRow] = av.x;
        As[aCol + 1][aRow] = av.y;
        As[aCol + 2][aRow] = av.z;
        As[aCol + 3][aRow] = av.w;
        if (BT) {
            // B is (N x K) row-major; Bs[k][n] = B[n][k]
            float4 bv = *(const float4*)&B[(size_t)(bn + aRow) * K + k0 + aCol];
            Bs[aCol + 0][aRow] = bv.x;
            Bs[aCol + 1][aRow] = bv.y;
            Bs[aCol + 2][aRow] = bv.z;
            Bs[aCol + 3][aRow] = bv.w;
        } else {
            // B is (K x N) row-major
            int bRow = tid >> 5;
            int bCol = (tid & 31) * 4;
            float4 bv = *(const float4*)&B[(size_t)(k0 + bRow) * N + bn + bCol];
            *(float4*)&Bs[bRow][bCol] = bv;
        }
        __syncthreads();

        #pragma unroll
        for (int k = 0; k < BK; k++) {
            float4 a0 = *(const float4*)&As[k][ty * 8];
            float4 a1 = *(const float4*)&As[k][ty * 8 + 4];
            float4 b0 = *(const float4*)&Bs[k][tx * 8];
            float4 b1 = *(const float4*)&Bs[k][tx * 8 + 4];
            float ra[8] = {a0.x, a0.y, a0.z, a0.w, a1.x, a1.y, a1.z, a1.w};
            float rb[8] = {b0.x, b0.y, b0.z, b0.w, b1.x, b1.y, b1.z, b1.w};
            #pragma unroll
            for (int i = 0; i < 8; i++)
                #pragma unroll
                for (int j = 0; j < 8; j++)
                    acc[i][j] += ra[i] * rb[j];
        }
        __syncthreads();
    }

    #pragma unroll
    for (int i = 0; i < 8; i++) {
        int row = bm + ty * 8 + i;
        float* cp = &C[(size_t)row * N + bn + tx * 8];
        if (MODE == 0) {
            *(float4*)&cp[0] = make_float4(acc[i][0], acc[i][1], acc[i][2], acc[i][3]);
            *(float4*)&cp[4] = make_float4(acc[i][4], acc[i][5], acc[i][6], acc[i][7]);
        } else if (MODE == 1) {
            float4 c0 = *(float4*)&cp[0];
            float4 c1 = *(float4*)&cp[4];
            c0.x += acc[i][0]; c0.y += acc[i][1]; c0.z += acc[i][2]; c0.w += acc[i][3];
            c1.x += acc[i][4]; c1.y += acc[i][5]; c1.z += acc[i][6]; c1.w += acc[i][7];
            *(float4*)&cp[0] = c0;
            *(float4*)&cp[4] = c1;
        } else {
            const float* bp = &bias[bn + tx * 8];
            *(float4*)&cp[0] = make_float4(acc[i][0] + bp[0], acc[i][1] + bp[1],
                                           acc[i][2] + bp[2], acc[i][3] + bp[3]);
            *(float4*)&cp[4] = make_float4(acc[i][4] + bp[4], acc[i][5] + bp[5],
                                           acc[i][6] + bp[6], acc[i][7] + bp[7]);
        }
    }
}

// ---------------- mask assembly ----------------
__global__ void k_initR() {
    int idx = blockIdx.x * blockDim.x + threadIdx.x;   // NN*NN threads
    int row = idx >> 11, col = idx & (NN - 1);
    g_R[idx] = g_A[idx] + g_A2[idx] + (row == col ? 1.0f : 0.0f);
}

__global__ void k_rownorm() {
    int r = blockIdx.x;
    __shared__ float sm[256];
    float s = 0.f;
    for (int c = threadIdx.x; c < NN; c += 256) {
        float v = g_R[(size_t)r * NN + c];
        s += v * v;
    }
    sm[threadIdx.x] = s;
    __syncthreads();
    for (int o = 128; o > 0; o >>= 1) {
        if (threadIdx.x < o) sm[threadIdx.x] += sm[threadIdx.x + o];
        __syncthreads();
    }
    if (threadIdx.x == 0) g_norm[r] = sqrtf(sm[0]);
}

__global__ void k_maskval(const void* __restrict__ ei) {
    int e = blockIdx.x * blockDim.x + threadIdx.x;
    if (e >= EE) return;
    int s = eidx(ei, e), d = eidx(ei, EE + e);
    float nrm = fmaxf(g_norm[s], 1e-12f);
    g_mv[e] = g_R[(size_t)s * NN + d] / nrm;
}

// ---------------- CSR by dst (counting sort) ----------------
__global__ void k_zerocnt() {
    int i = blockIdx.x * blockDim.x + threadIdx.x;
    if (i < NN) { g_cnt[i] = 0; g_cur[i] = 0; }
}

__global__ void k_count(const void* __restrict__ ei) {
    int e = blockIdx.x * blockDim.x + threadIdx.x;
    if (e >= EE) return;
    atomicAdd(&g_cnt[eidx(ei, EE + e)], 1);
}

__global__ void k_scan() {
    __shared__ int sm[NN];
    for (int i = threadIdx.x; i < NN; i += blockDim.x) sm[i] = g_cnt[i];
    __syncthreads();
    if (threadIdx.x == 0) {
        int run = 0;
        for (int i = 0; i < NN; i++) { int c = sm[i]; sm[i] = run; run += c; }
        g_off[NN] = run;
    }
    __syncthreads();
    for (int i = threadIdx.x; i < NN; i += blockDim.x) g_off[i] = sm[i];
}

__global__ void k_scatter(const void* __restrict__ ei) {
    int e = blockIdx.x * blockDim.x + threadIdx.x;
    if (e >= EE) return;
    int s = eidx(ei, e), d = eidx(ei, EE + e);
    int pos = g_off[d] + atomicAdd(&g_cur[d], 1);
    g_ssrc[pos] = s;
    g_seid[pos] = e;
}

// ---------------- attention ----------------
// per node n: warp h computes s_i[n,h] = <xh[n,h,:], att_i[h,:]>, s_j likewise
__global__ void k_s(const float* __restrict__ att) {
    int n = blockIdx.x;
    int w = threadIdx.x >> 5;
    int lane = threadIdx.x & 31;
    const float* row = g_xh + (size_t)n * (HH * CC) + w * CC;
    const float* ai = att + w * (2 * CC);
    const float* aj = ai + CC;
    float vi = 0.f, vj = 0.f;
    #pragma unroll
    for (int c = lane; c < CC; c += 32) {
        float v = row[c];
        vi += v * ai[c];
        vj += v * aj[c];
    }
    #pragma unroll
    for (int o = 16; o > 0; o >>= 1) {
        vi += __shfl_xor_sync(0xffffffffu, vi, o);
        vj += __shfl_xor_sync(0xffffffffu, vj, o);
    }
    if (lane == 0) { g_si[n * HH + w] = vi; g_sj[n * HH + w] = vj; }
}

__global__ void k_z(const void* __restrict__ ei) {
    int e = blockIdx.x * blockDim.x + threadIdx.x;
    if (e >= EE) return;
    int s = eidx(ei, e), d = eidx(ei, EE + e);
    float mv = g_mv[e];
    #pragma unroll
    for (int h = 0; h < HH; h++) {
        float a = g_si[d * HH + h] + g_sj[s * HH + h];
        a = (a >= 0.f) ? a : NEG * a;
        g_z[h * EE + e] = a * mv;
    }
}

__global__ void k_hmax() {
    int h = blockIdx.x;
    __shared__ float sm[1024];
    float m = -1e30f;
    for (int e = threadIdx.x; e < EE; e += 1024) m = fmaxf(m, g_z[h * EE + e]);
    sm[threadIdx.x] = m;
    __syncthreads();
    for (int o = 512; o > 0; o >>= 1) {
        if (threadIdx.x < o) sm[threadIdx.x] = fmaxf(sm[threadIdx.x], sm[threadIdx.x + o]);
        __syncthreads();
    }
    if (threadIdx.x == 0) g_hmax[h] = sm[0];
}

__global__ void k_expsum() {
    int h = blockIdx.x;
    float m = g_hmax[h];
    __shared__ float sm[1024];
    float s = 0.f;
    for (int e = threadIdx.x; e < EE; e += 1024) {
        float ex = expf(g_z[h * EE + e] - m);
        g_z[h * EE + e] = ex;    // in place: g_z becomes exp values
        s += ex;
    }
    sm[threadIdx.x] = s;
    __syncthreads();
    for (int o = 512; o > 0; o >>= 1) {
        if (threadIdx.x < o) sm[threadIdx.x] += sm[threadIdx.x + o];
        __syncthreads();
    }
    if (threadIdx.x == 0) g_Zs[h] = sm[0];
}

// one block per dst node, 128 threads = channels; relu(mean over heads)
__global__ void k_aggregate(float* __restrict__ out) {
    int d = blockIdx.x;
    int c = threadIdx.x;
    int s0 = g_off[d], s1 = g_off[d + 1];
    float acc = 0.f;
    #pragma unroll
    for (int h = 0; h < HH; h++) {
        float a = 0.f;
        float invZ = 1.0f / g_Zs[h];
        for (int idx = s0; idx < s1; idx++) {
            int s = g_ssrc[idx];
            int e = g_seid[idx];
            a += g_z[h * EE + e] * g_xh[(size_t)s * (HH * CC) + h * CC + c];
        }
        acc += a * invZ;
    }
    acc *= (1.0f / HH);
    out[d * CC + c] = fmaxf(acc, 0.f);
}

__global__ void k_final(float* __restrict__ out) {
    int i = blockIdx.x * blockDim.x + threadIdx.x;
    out[i] = g_h2[i] + g_xskip[i];
}

// ---------------- launch ----------------
extern "C" void kernel_launch(void* const* d_in, const int* in_sizes, int n_in,
                              void* d_out, int out_size) {
    const float* x      = (const float*)d_in[0];
    const void*  ei     = d_in[1];
    const float* lin_w0 = (const float*)d_in[2];
    const float* att0   = (const float*)d_in[3];
    const float* lin_w1 = (const float*)d_in[4];
    const float* att1   = (const float*)d_in[5];
    const float* skip_w = (const float*)d_in[6];
    const float* skip_b = (const float*)d_in[7];
    float* out = (float*)d_out;

    float *pA, *pA2, *pR, *pXh, *pH1, *pH2, *pXs;
    cudaGetSymbolAddress((void**)&pA,  g_A);
    cudaGetSymbolAddress((void**)&pA2, g_A2);
    cudaGetSymbolAddress((void**)&pR,  g_R);
    cudaGetSymbolAddress((void**)&pXh, g_xh);
    cudaGetSymbolAddress((void**)&pH1, g_h1);
    cudaGetSymbolAddress((void**)&pH2, g_h2);
    cudaGetSymbolAddress((void**)&pXs, g_xskip);

    k_detect<<<1, 256>>>((const unsigned*)ei);

    // build A' = A + I
    k_zeroA<<<(NN * NN / 4) / 256, 256>>>();
    k_buildA<<<EE / 256, 256>>>(ei);
    k_diag<<<NN / 256, 256>>>();

    // mask: R = I + A' + A'^2 + A'^3 + A'^4  via  A2=A'A', A3=A2*A', A4=A2*A2
    dim3 g16(NN / BN, NN / BM);
    gemm_f32<false, 0><<<g16, 256>>>(pA, pA, pA2, nullptr, NN, NN, NN);
    k_initR<<<(NN * NN) / 256, 256>>>();
    gemm_f32<false, 1><<<g16, 256>>>(pA2, pA, pR, nullptr, NN, NN, NN);
    gemm_f32<false, 1><<<g16, 256>>>(pA2, pA2, pR, nullptr, NN, NN, NN);
    k_rownorm<<<NN, 256>>>();
    k_maskval<<<EE / 256, 256>>>(ei);

    // CSR by dst
    k_zerocnt<<<NN / 256, 256>>>();
    k_count<<<EE / 256, 256>>>(ei);
    k_scan<<<1, 256>>>();
    k_scatter<<<EE / 256, 256>>>(ei);

    // ---- layer 1 ----
    gemm_f32<true, 0><<<dim3((HH * CC) / BN, NN / BM), 256>>>(x, lin_w0, pXh, nullptr, NN, HH * CC, CC);
    k_s<<<NN, 256>>>(att0);
    k_z<<<EE / 256, 256>>>(ei);
    k_hmax<<<HH, 1024>>>();
    k_expsum<<<HH, 1024>>>();
    k_aggregate<<<NN, CC>>>(pH1);

    // ---- layer 2 ----
    gemm_f32<true, 0><<<dim3((HH * CC) / BN, NN / BM), 256>>>(pH1, lin_w1, pXh, nullptr, NN, HH * CC, CC);
    k_s<<<NN, 256>>>(att1);
    k_z<<<EE / 256, 256>>>(ei);
    k_hmax<<<HH, 1024>>>();
    k_expsum<<<HH, 1024>>>();
    k_aggregate<<<NN, CC>>>(pH2);

    // skip + final
    gemm_f32<true, 2><<<dim3(CC / BN, NN / BM), 256>>>(x, skip_w, pXs, skip_b, NN, CC, CC);
    k_final<<<(NN * CC) / 256, 256>>>(out);
}

// round 3
// speedup vs baseline: 3.2781x; 3.2781x over previous
#include <cuda_runtime.h>
#include <cuda_bf16.h>
#include <cstdint>
#include <math.h>

#define NN 2048
#define EE 65536
#define HH 8
#define CC 128
#define NEG 0.2f

#define BM 128
#define BN 128
#define BK 8

// ---------------- device scratch (static: no allocations allowed) ----------------
__device__ float          g_A [NN*NN];     // fp32 A' = adj + I
__device__ float          g_R [NN*NN];     // fp32 mask accumulator
__device__ __nv_bfloat16  g_Abf  [NN*NN];
__device__ __nv_bfloat16  g_ATbf [NN*NN];
__device__ __nv_bfloat16  g_A2bf [NN*NN];
__device__ __nv_bfloat16  g_A2Tbf[NN*NN];
__device__ __nv_bfloat16  g_STbf [NN*NN];  // (A + A2)^T in bf16
__device__ float g_xh[NN*HH*CC];
__device__ float g_si[NN*HH];
__device__ float g_sj[NN*HH];
__device__ float g_z [HH*EE];
__device__ float g_mv[EE];
__device__ float g_hmax[HH];
__device__ float g_Zs[HH];
__device__ float g_norm[NN];
__device__ int   g_cnt[NN];
__device__ int   g_cur[NN];
__device__ int   g_off[NN+1];
__device__ int   g_ssrc[EE];
__device__ int   g_seid[EE];
__device__ float g_h1[NN*CC];
__device__ float g_h2[NN*CC];
__device__ float g_xskip[NN*CC];
__device__ int   g_is64;

// edge index load that works for int32 or int64 buffers
__device__ __forceinline__ int eidx(const void* ei, int pos) {
    if (g_is64) return (int)((const long long*)ei)[pos];
    return ((const int*)ei)[pos];
}

// ---------------- dtype detection ----------------
__global__ void k_detect(const unsigned* __restrict__ w) {
    __shared__ int anynz;
    if (threadIdx.x == 0) anynz = 0;
    __syncthreads();
    unsigned v = 0;
    for (int i = 1 + 2 * threadIdx.x; i < 8192; i += 2 * blockDim.x) v |= w[i];
    if (v) anynz = 1;
    __syncthreads();
    if (threadIdx.x == 0) g_is64 = anynz ? 0 : 1;
}

// ---------------- adjacency build ----------------
__global__ void k_zeroA() {
    int i = blockIdx.x * blockDim.x + threadIdx.x;
    ((float4*)g_A)[i] = make_float4(0.f, 0.f, 0.f, 0.f);
}

__global__ void k_buildA(const void* __restrict__ ei) {
    int e = blockIdx.x * blockDim.x + threadIdx.x;
    if (e >= EE) return;
    int s = eidx(ei, e), d = eidx(ei, EE + e);
    atomicAdd(&g_A[s * NN + d], 1.0f);
}

__global__ void k_diag() {
    int i = blockIdx.x * blockDim.x + threadIdx.x;
    if (i < NN) g_A[i * NN + i] += 1.0f;
}

// ---------------- fp32 -> bf16 convert + transpose ----------------
__global__ void k_cvtA() {
    int i = blockIdx.x * blockDim.x + threadIdx.x;   // NN*NN/4 threads
    float4 v = ((const float4*)g_A)[i];
    __nv_bfloat162 lo = __float22bfloat162_rn(make_float2(v.x, v.y));
    __nv_bfloat162 hi = __float22bfloat162_rn(make_float2(v.z, v.w));
    uint2 p;
    p.x = *(uint32_t*)&lo;
    p.y = *(uint32_t*)&hi;
    ((uint2*)g_Abf)[i] = p;
}

__global__ void k_transposeA() {
    __shared__ float tile[32][33];
    int bx = blockIdx.x * 32, by = blockIdx.y * 32;
    #pragma unroll
    for (int r = 0; r < 32; r += 8)
        tile[threadIdx.y + r][threadIdx.x] = g_A[(size_t)(by + threadIdx.y + r) * NN + bx + threadIdx.x];
    __syncthreads();
    #pragma unroll
    for (int r = 0; r < 32; r += 8)
        g_ATbf[(size_t)(bx + threadIdx.y + r) * NN + by + threadIdx.x] =
            __float2bfloat16(tile[threadIdx.x][threadIdx.y + r]);
}

// STbf = ATbf + A2Tbf  (exact small integers)
__global__ void k_ST() {
    int i = blockIdx.x * blockDim.x + threadIdx.x;   // NN*NN/2 threads
    __nv_bfloat162 a = ((const __nv_bfloat162*)g_ATbf)[i];
    __nv_bfloat162 b = ((const __nv_bfloat162*)g_A2Tbf)[i];
    float2 fa = __bfloat1622float2(a);
    float2 fb = __bfloat1622float2(b);
    ((__nv_bfloat162*)g_STbf)[i] =
        __float22bfloat162_rn(make_float2(fa.x + fb.x, fa.y + fb.y));
}

// ================= HMMA bf16 GEMM (mma.sync m16n8k16) =================
// D[m][n] = sum_k Aop[m][k] * Bop[n][k], Aop/Bop row-major [2048 x 2048] bf16.
// MODE 0: write bf16 matrix; MODE 1: accumulate fp32 into Cout.
// CTA tile 128x128, BK=64 (128B rows, XOR-swizzled), double-buffered SMEM.
// 8 warps in 4(M) x 2(N): warp tile 32x64.

#define GKC    64                 // K elems per chunk
#define NCHUNK (NN / GKC)         // 32
#define SM_TILE 16384             // 128 rows x 128B
#define GEMM_SMEM (4 * SM_TILE)   // A0,A1,B0,B1

__device__ __forceinline__ uint32_t smem_u32(const void* p) {
    uint32_t a;
    asm("{ .reg .u64 t; cvta.to.shared.u64 t, %1; cvt.u32.u64 %0, t; }" : "=r"(a) : "l"(p));
    return a;
}

__device__ __forceinline__ void ldmx4(uint32_t addr, uint32_t& r0, uint32_t& r1,
                                      uint32_t& r2, uint32_t& r3) {
    asm volatile("ldmatrix.sync.aligned.m8n8.x4.shared.b16 {%0,%1,%2,%3}, [%4];"
                 : "=r"(r0), "=r"(r1), "=r"(r2), "=r"(r3) : "r"(addr));
}

__device__ __forceinline__ void mma16816(float* d, uint32_t a0, uint32_t a1,
                                         uint32_t a2, uint32_t a3,
                                         uint32_t b0, uint32_t b1) {
    asm volatile("mma.sync.aligned.m16n8k16.row.col.f32.bf16.bf16.f32 "
                 "{%0,%1,%2,%3}, {%4,%5,%6,%7}, {%8,%9}, {%0,%1,%2,%3};"
                 : "+f"(d[0]), "+f"(d[1]), "+f"(d[2]), "+f"(d[3])
                 : "r"(a0), "r"(a1), "r"(a2), "r"(a3), "r"(b0), "r"(b1));
}

template<int MODE>
__global__ __launch_bounds__(256, 1)
void gemm_bf16mma(const __nv_bfloat16* __restrict__ Aop,
                  const __nv_bfloat16* __restrict__ Bop,
                  void* __restrict__ Cout)
{
    extern __shared__ __align__(1024) char smem[];
    const uint32_t sbase = smem_u32(smem);
    const int tid  = threadIdx.x;
    const int lane = tid & 31;
    const int w    = tid >> 5;
    const int wm   = w & 3;          // 0..3 (M)
    const int wn   = w >> 2;         // 0..1 (N)
    const int bm = blockIdx.y * 128, bn = blockIdx.x * 128;

    // ---- global load slots: 4 x 16B per tile per thread ----
    const __nv_bfloat16* aptr[4];
    const __nv_bfloat16* bptr[4];
    uint32_t soff[4];
    #pragma unroll
    for (int i = 0; i < 4; i++) {
        int q = tid + 256 * i;
        int row = q >> 3, seg = q & 7;
        aptr[i] = Aop + (size_t)(bm + row) * NN + seg * 8;
        bptr[i] = Bop + (size_t)(bn + row) * NN + seg * 8;
        soff[i] = row * 128 + (((row & 7) << 4) ^ (seg * 16));   // swizzled
    }

    // ---- ldmatrix address components ----
    // A: 16x16 tiles; thread t -> row (t%16), col half (t/16)
    const int a_r  = lane & 15;
    const int a_hi = lane >> 4;
    const int a_xor = (a_r & 7) << 4;
    // rows for the two m16 tiles of this warp
    const int arow0 = wm * 32 + a_r;
    // B: 16(n)x16(k) tiles; groups of 8 lanes
    const int b_g = lane >> 3, b_w = lane & 7;
    const int b_xor = b_w << 4;
    const int brow_base = wn * 64 + ((b_g >> 1) << 3) + b_w;
    const int b_khi = (b_g & 1) * 16;

    float acc[2][8][4];
    #pragma unroll
    for (int i = 0; i < 2; i++)
        #pragma unroll
        for (int j = 0; j < 8; j++)
            #pragma unroll
            for (int t = 0; t < 4; t++) acc[i][j][t] = 0.f;

    // ---- prologue: load + store chunk 0 ----
    uint4 va[4], vb[4];
    #pragma unroll
    for (int i = 0; i < 4; i++) { va[i] = *(const uint4*)aptr[i]; aptr[i] += GKC; }
    #pragma unroll
    for (int i = 0; i < 4; i++) { vb[i] = *(const uint4*)bptr[i]; bptr[i] += GKC; }
    #pragma unroll
    for (int i = 0; i < 4; i++)
        asm volatile("st.shared.v4.b32 [%0], {%1,%2,%3,%4};"
                     :: "r"(sbase + soff[i]), "r"(va[i].x), "r"(va[i].y), "r"(va[i].z), "r"(va[i].w) : "memory");
    #pragma unroll
    for (int i = 0; i < 4; i++)
        asm volatile("st.shared.v4.b32 [%0], {%1,%2,%3,%4};"
                     :: "r"(sbase + 2 * SM_TILE + soff[i]), "r"(vb[i].x), "r"(vb[i].y), "r"(vb[i].z), "r"(vb[i].w) : "memory");
    __syncthreads();

    for (int c = 0; c < NCHUNK; c++) {
        const int buf = c & 1;
        const uint32_t sA = sbase + buf * SM_TILE;
        const uint32_t sB = sbase + 2 * SM_TILE + buf * SM_TILE;

        if (c + 1 < NCHUNK) {
            #pragma unroll
            for (int i = 0; i < 4; i++) { va[i] = *(const uint4*)aptr[i]; aptr[i] += GKC; }
            #pragma unroll
            for (int i = 0; i < 4; i++) { vb[i] = *(const uint4*)bptr[i]; bptr[i] += GKC; }
        }

        // ---- compute on buffer buf ----
        #pragma unroll
        for (int ks = 0; ks < 4; ks++) {
            uint32_t a[2][4];
            #pragma unroll
            for (int im = 0; im < 2; im++) {
                int row = arow0 + im * 16;
                uint32_t addr = sA + row * 128 + (a_xor ^ (ks * 32 + a_hi * 16));
                ldmx4(addr, a[im][0], a[im][1], a[im][2], a[im][3]);
            }
            uint32_t b[8][2];
            #pragma unroll
            for (int jn = 0; jn < 4; jn++) {
                int row = brow_base + jn * 16;
                uint32_t addr = sB + row * 128 + (b_xor ^ (ks * 32 + b_khi));
                uint32_t r0, r1, r2, r3;
                ldmx4(addr, r0, r1, r2, r3);
                b[2 * jn][0] = r0; b[2 * jn][1] = r1;
                b[2 * jn + 1][0] = r2; b[2 * jn + 1][1] = r3;
            }
            #pragma unroll
            for (int im = 0; im < 2; im++)
                #pragma unroll
                for (int jf = 0; jf < 8; jf++)
                    mma16816(acc[im][jf], a[im][0], a[im][1], a[im][2], a[im][3],
                             b[jf][0], b[jf][1]);
        }

        if (c + 1 < NCHUNK) {
            const uint32_t dA = sbase + (buf ^ 1) * SM_TILE;
            const uint32_t dB = sbase + 2 * SM_TILE + (buf ^ 1) * SM_TILE;
            #pragma unroll
            for (int i = 0; i < 4; i++)
                asm volatile("st.shared.v4.b32 [%0], {%1,%2,%3,%4};"
                             :: "r"(dA + soff[i]), "r"(va[i].x), "r"(va[i].y), "r"(va[i].z), "r"(va[i].w) : "memory");
            #pragma unroll
            for (int i = 0; i < 4; i++)
                asm volatile("st.shared.v4.b32 [%0], {%1,%2,%3,%4};"
                             :: "r"(dB + soff[i]), "r"(vb[i].x), "r"(vb[i].y), "r"(vb[i].z), "r"(vb[i].w) : "memory");
        }
        __syncthreads();
    }

    // ---- epilogue ----
    // acc[im][jf] fragment: rows m = bm + wm*32 + im*16 + lane/4 (+8),
    //                       cols n = bn + wn*64 + jf*8 + 2*(lane%4) (+1)
    const int mrow = bm + wm * 32 + (lane >> 2);
    const int ncol = bn + wn * 64 + 2 * (lane & 3);
    #pragma unroll
    for (int im = 0; im < 2; im++) {
        #pragma unroll
        for (int half = 0; half < 2; half++) {
            int m = mrow + im * 16 + half * 8;
            #pragma unroll
            for (int jf = 0; jf < 8; jf++) {
                int n = ncol + jf * 8;
                float v0 = acc[im][jf][2 * half];
                float v1 = acc[im][jf][2 * half + 1];
                if (MODE == 0) {
                    __nv_bfloat162 h = __float22bfloat162_rn(make_float2(v0, v1));
                    *(__nv_bfloat162*)((__nv_bfloat16*)Cout + (size_t)m * NN + n) = h;
                } else {
                    float2* cp = (float2*)((float*)Cout + (size_t)m * NN + n);
                    float2 cv = *cp;
                    cv.x += v0; cv.y += v1;
                    *cp = cv;
                }
            }
        }
    }
}

// ---------------- fp32 SIMT GEMM (small lin layers): C = A*B^T ----------------
template<bool BT, int MODE>
__global__ __launch_bounds__(256, 2)
void gemm_f32(const float* __restrict__ A, const float* __restrict__ B,
              float* __restrict__ C, const float* __restrict__ bias,
              int M, int N, int K)
{
    __shared__ float As[BK][BM];
    __shared__ float Bs[BK][BN];
    const int tid = threadIdx.x;
    const int bm = blockIdx.y * BM;
    const int bn = blockIdx.x * BN;
    const int tx = tid & 15;
    const int ty = tid >> 4;
    const int aRow = tid >> 1;
    const int aCol = (tid & 1) * 4;

    float acc[8][8];
    #pragma unroll
    for (int i = 0; i < 8; i++)
        #pragma unroll
        for (int j = 0; j < 8; j++) acc[i][j] = 0.f;

    for (int k0 = 0; k0 < K; k0 += BK) {
        float4 av = *(const float4*)&A[(size_t)(bm + aRow) * K + k0 + aCol];
        As[aCol + 0][aRow] = av.x;
        As[aCol + 1][aRow] = av.y;
        As[aCol + 2][aRow] = av.z;
        As[aCol + 3][aRow] = av.w;
        if (BT) {
            float4 bv = *(const float4*)&B[(size_t)(bn + aRow) * K + k0 + aCol];
            Bs[aCol + 0][aRow] = bv.x;
            Bs[aCol + 1][aRow] = bv.y;
            Bs[aCol + 2][aRow] = bv.z;
            Bs[aCol + 3][aRow] = bv.w;
        } else {
            int bRow = tid >> 5;
            int bCol = (tid & 31) * 4;
            float4 bv = *(const float4*)&B[(size_t)(k0 + bRow) * N + bn + bCol];
            *(float4*)&Bs[bRow][bCol] = bv;
        }
        __syncthreads();

        #pragma unroll
        for (int k = 0; k < BK; k++) {
            float4 a0 = *(const float4*)&As[k][ty * 8];
            float4 a1 = *(const float4*)&As[k][ty * 8 + 4];
            float4 b0 = *(const float4*)&Bs[k][tx * 8];
            float4 b1 = *(const float4*)&Bs[k][tx * 8 + 4];
            float ra[8] = {a0.x, a0.y, a0.z, a0.w, a1.x, a1.y, a1.z, a1.w};
            float rb[8] = {b0.x, b0.y, b0.z, b0.w, b1.x, b1.y, b1.z, b1.w};
            #pragma unroll
            for (int i = 0; i < 8; i++)
                #pragma unroll
                for (int j = 0; j < 8; j++)
                    acc[i][j] += ra[i] * rb[j];
        }
        __syncthreads();
    }

    #pragma unroll
    for (int i = 0; i < 8; i++) {
        int row = bm + ty * 8 + i;
        float* cp = &C[(size_t)row * N + bn + tx * 8];
        if (MODE == 0) {
            *(float4*)&cp[0] = make_float4(acc[i][0], acc[i][1], acc[i][2], acc[i][3]);
            *(float4*)&cp[4] = make_float4(acc[i][4], acc[i][5], acc[i][6], acc[i][7]);
        } else {
            const float* bp = &bias[bn + tx * 8];
            *(float4*)&cp[0] = make_float4(acc[i][0] + bp[0], acc[i][1] + bp[1],
                                           acc[i][2] + bp[2], acc[i][3] + bp[3]);
            *(float4*)&cp[4] = make_float4(acc[i][4] + bp[4], acc[i][5] + bp[5],
                                           acc[i][6] + bp[6], acc[i][7] + bp[7]);
        }
    }
}

// ---------------- mask assembly ----------------
__global__ void k_initR() {
    int idx = blockIdx.x * blockDim.x + threadIdx.x;
    int row = idx >> 11, col = idx & (NN - 1);
    g_R[idx] = g_A[idx] + __bfloat162float(g_A2bf[idx]) + (row == col ? 1.0f : 0.0f);
}

__global__ void k_rownorm() {
    int r = blockIdx.x;
    __shared__ float sm[256];
    float s = 0.f;
    for (int c = threadIdx.x; c < NN; c += 256) {
        float v = g_R[(size_t)r * NN + c];
        s += v * v;
    }
    sm[threadIdx.x] = s;
    __syncthreads();
    for (int o = 128; o > 0; o >>= 1) {
        if (threadIdx.x < o) sm[threadIdx.x] += sm[threadIdx.x + o];
        __syncthreads();
    }
    if (threadIdx.x == 0) g_norm[r] = sqrtf(sm[0]);
}

__global__ void k_maskval(const void* __restrict__ ei) {
    int e = blockIdx.x * blockDim.x + threadIdx.x;
    if (e >= EE) return;
    int s = eidx(ei, e), d = eidx(ei, EE + e);
    float nrm = fmaxf(g_norm[s], 1e-12f);
    g_mv[e] = g_R[(size_t)s * NN + d] / nrm;
}

// ---------------- CSR by dst (counting sort) ----------------
__global__ void k_zerocnt() {
    int i = blockIdx.x * blockDim.x + threadIdx.x;
    if (i < NN) { g_cnt[i] = 0; g_cur[i] = 0; }
}

__global__ void k_count(const void* __restrict__ ei) {
    int e = blockIdx.x * blockDim.x + threadIdx.x;
    if (e >= EE) return;
    atomicAdd(&g_cnt[eidx(ei, EE + e)], 1);
}

__global__ void k_scan() {
    __shared__ int sm[NN];
    for (int i = threadIdx.x; i < NN; i += blockDim.x) sm[i] = g_cnt[i];
    __syncthreads();
    if (threadIdx.x == 0) {
        int run = 0;
        for (int i = 0; i < NN; i++) { int c = sm[i]; sm[i] = run; run += c; }
        g_off[NN] = run;
    }
    __syncthreads();
    for (int i = threadIdx.x; i < NN; i += blockDim.x) g_off[i] = sm[i];
}

__global__ void k_scatter(const void* __restrict__ ei) {
    int e = blockIdx.x * blockDim.x + threadIdx.x;
    if (e >= EE) return;
    int s = eidx(ei, e), d = eidx(ei, EE + e);
    int pos = g_off[d] + atomicAdd(&g_cur[d], 1);
    g_ssrc[pos] = s;
    g_seid[pos] = e;
}

// ---------------- attention ----------------
__global__ void k_s(const float* __restrict__ att) {
    int n = blockIdx.x;
    int w = threadIdx.x >> 5;
    int lane = threadIdx.x & 31;
    const float* row = g_xh + (size_t)n * (HH * CC) + w * CC;
    const float* ai = att + w * (2 * CC);
    const float* aj = ai + CC;
    float vi = 0.f, vj = 0.f;
    #pragma unroll
    for (int c = lane; c < CC; c += 32) {
        float v = row[c];
        vi += v * ai[c];
        vj += v * aj[c];
    }
    #pragma unroll
    for (int o = 16; o > 0; o >>= 1) {
        vi += __shfl_xor_sync(0xffffffffu, vi, o);
        vj += __shfl_xor_sync(0xffffffffu, vj, o);
    }
    if (lane == 0) { g_si[n * HH + w] = vi; g_sj[n * HH + w] = vj; }
}

__global__ void k_z(const void* __restrict__ ei) {
    int e = blockIdx.x * blockDim.x + threadIdx.x;
    if (e >= EE) return;
    int s = eidx(ei, e), d = eidx(ei, EE + e);
    float mv = g_mv[e];
    #pragma unroll
    for (int h = 0; h < HH; h++) {
        float a = g_si[d * HH + h] + g_sj[s * HH + h];
        a = (a >= 0.f) ? a : NEG * a;
        g_z[h * EE + e] = a * mv;
    }
}

__global__ void k_hmax() {
    int h = blockIdx.x;
    __shared__ float sm[1024];
    float m = -1e30f;
    for (int e = threadIdx.x; e < EE; e += 1024) m = fmaxf(m, g_z[h * EE + e]);
    sm[threadIdx.x] = m;
    __syncthreads();
    for (int o = 512; o > 0; o >>= 1) {
        if (threadIdx.x < o) sm[threadIdx.x] = fmaxf(sm[threadIdx.x], sm[threadIdx.x + o]);
        __syncthreads();
    }
    if (threadIdx.x == 0) g_hmax[h] = sm[0];
}

__global__ void k_expsum() {
    int h = blockIdx.x;
    float m = g_hmax[h];
    __shared__ float sm[1024];
    float s = 0.f;
    for (int e = threadIdx.x; e < EE; e += 1024) {
        float ex = expf(g_z[h * EE + e] - m);
        g_z[h * EE + e] = ex;
        s += ex;
    }
    sm[threadIdx.x] = s;
    __syncthreads();
    for (int o = 512; o > 0; o >>= 1) {
        if (threadIdx.x < o) sm[threadIdx.x] += sm[threadIdx.x + o];
        __syncthreads();
    }
    if (threadIdx.x == 0) g_Zs[h] = sm[0];
}

__global__ void k_aggregate(float* __restrict__ out) {
    int d = blockIdx.x;
    int c = threadIdx.x;
    int s0 = g_off[d], s1 = g_off[d + 1];
    float acc = 0.f;
    #pragma unroll
    for (int h = 0; h < HH; h++) {
        float a = 0.f;
        float invZ = 1.0f / g_Zs[h];
        for (int idx = s0; idx < s1; idx++) {
            int s = g_ssrc[idx];
            int e = g_seid[idx];
            a += g_z[h * EE + e] * g_xh[(size_t)s * (HH * CC) + h * CC + c];
        }
        acc += a * invZ;
    }
    acc *= (1.0f / HH);
    out[d * CC + c] = fmaxf(acc, 0.f);
}

__global__ void k_final(float* __restrict__ out) {
    int i = blockIdx.x * blockDim.x + threadIdx.x;
    out[i] = g_h2[i] + g_xskip[i];
}

// ---------------- launch ----------------
extern "C" void kernel_launch(void* const* d_in, const int* in_sizes, int n_in,
                              void* d_out, int out_size) {
    const float* x      = (const float*)d_in[0];
    const void*  ei     = d_in[1];
    const float* lin_w0 = (const float*)d_in[2];
    const float* att0   = (const float*)d_in[3];
    const float* lin_w1 = (const float*)d_in[4];
    const float* att1   = (const float*)d_in[5];
    const float* skip_w = (const float*)d_in[6];
    const float* skip_b = (const float*)d_in[7];
    float* out = (float*)d_out;

    void *pAbf, *pATbf, *pA2bf, *pA2Tbf, *pSTbf, *pR;
    float *pXh, *pH1, *pH2, *pXs;
    cudaGetSymbolAddress(&pAbf,   g_Abf);
    cudaGetSymbolAddress(&pATbf,  g_ATbf);
    cudaGetSymbolAddress(&pA2bf,  g_A2bf);
    cudaGetSymbolAddress(&pA2Tbf, g_A2Tbf);
    cudaGetSymbolAddress(&pSTbf,  g_STbf);
    cudaGetSymbolAddress(&pR,     g_R);
    cudaGetSymbolAddress((void**)&pXh, g_xh);
    cudaGetSymbolAddress((void**)&pH1, g_h1);
    cudaGetSymbolAddress((void**)&pH2, g_h2);
    cudaGetSymbolAddress((void**)&pXs, g_xskip);

    cudaFuncSetAttribute(gemm_bf16mma<0>, cudaFuncAttributeMaxDynamicSharedMemorySize, GEMM_SMEM);
    cudaFuncSetAttribute(gemm_bf16mma<1>, cudaFuncAttributeMaxDynamicSharedMemorySize, GEMM_SMEM);

    k_detect<<<1, 256>>>((const unsigned*)ei);

    // build A' = adj + I (fp32), then bf16 copies A, A^T
    k_zeroA<<<(NN * NN / 4) / 256, 256>>>();
    k_buildA<<<EE / 256, 256>>>(ei);
    k_diag<<<NN / 256, 256>>>();
    k_cvtA<<<(NN * NN / 4) / 256, 256>>>();
    k_transposeA<<<dim3(NN / 32, NN / 32), dim3(32, 8)>>>();

    // A2 = A*A   and   A2^T = A^T*A^T   (HMMA, bf16-exact)
    dim3 gt(NN / 128, NN / 128);
    gemm_bf16mma<0><<<gt, 256, GEMM_SMEM>>>((const __nv_bfloat16*)pAbf,
                                            (const __nv_bfloat16*)pATbf, pA2bf);
    gemm_bf16mma<0><<<gt, 256, GEMM_SMEM>>>((const __nv_bfloat16*)pATbf,
                                            (const __nv_bfloat16*)pAbf, pA2Tbf);

    // R = I + A + A2 ; ST = (A + A2)^T ; R += A2 * (A + A2)  -> I+A+A2+A3+A4
    k_initR<<<(NN * NN) / 256, 256>>>();
    k_ST<<<(NN * NN / 2) / 256, 256>>>();
    gemm_bf16mma<1><<<gt, 256, GEMM_SMEM>>>((const __nv_bfloat16*)pA2bf,
                                            (const __nv_bfloat16*)pSTbf, pR);

    k_rownorm<<<NN, 256>>>();
    k_maskval<<<EE / 256, 256>>>(ei);

    // CSR by dst
    k_zerocnt<<<NN / 256, 256>>>();
    k_count<<<EE / 256, 256>>>(ei);
    k_scan<<<1, 256>>>();
    k_scatter<<<EE / 256, 256>>>(ei);

    // ---- layer 1 ----
    gemm_f32<true, 0><<<dim3((HH * CC) / BN, NN / BM), 256>>>(x, lin_w0, pXh, nullptr, NN, HH * CC, CC);
    k_s<<<NN, 256>>>(att0);
    k_z<<<EE / 256, 256>>>(ei);
    k_hmax<<<HH, 1024>>>();
    k_expsum<<<HH, 1024>>>();
    k_aggregate<<<NN, CC>>>(pH1);

    // ---- layer 2 ----
    gemm_f32<true, 0><<<dim3((HH * CC) / BN, NN / BM), 256>>>(pH1, lin_w1, pXh, nullptr, NN, HH * CC, CC);
    k_s<<<NN, 256>>>(att1);
    k_z<<<EE / 256, 256>>>(ei);
    k_hmax<<<HH, 1024>>>();
    k_expsum<<<HH, 1024>>>();
    k_aggregate<<<NN, CC>>>(pH2);

    // skip + final
    gemm_f32<true, 1><<<dim3(CC / BN, NN / BM), 256>>>(x, skip_w, pXs, skip_b, NN, CC, CC);
    k_final<<<(NN * CC) / 256, 256>>>(out);
}

// round 4
// speedup vs baseline: 3.8422x; 1.1721x over previous
#include <cuda_runtime.h>
#include <cuda_bf16.h>
#include <cstdint>
#include <math.h>

#define NN 2048
#define EE 65536
#define HH 8
#define CC 128
#define NEG 0.2f

#define BM 128
#define BN 128
#define BK 8

// ---------------- device scratch (static: no allocations allowed) ----------------
__device__ float          g_A [NN*NN];     // fp32 A' = adj + I
__device__ float          g_R [NN*NN];     // fp32 mask accumulator
__device__ __nv_bfloat16  g_Abf  [NN*NN];
__device__ __nv_bfloat16  g_ATbf [NN*NN];
__device__ __nv_bfloat16  g_A2bf [NN*NN];
__device__ __nv_bfloat16  g_STbf [NN*NN];  // (A + A2)^T in bf16
__device__ float g_xh[NN*HH*CC];
__device__ float g_si[NN*HH];
__device__ float g_sj[NN*HH];
__device__ float g_z [HH*EE];
__device__ float g_mv[EE];
__device__ float g_Zs[HH];
__device__ float g_norm[NN];
__device__ int   g_cnt[NN];
__device__ int   g_cur[NN];
__device__ int   g_off[NN+1];
__device__ int   g_ssrc[EE];
__device__ int   g_seid[EE];
__device__ float g_h1[NN*CC];
__device__ float g_h2[NN*CC];
__device__ float g_xskip[NN*CC];
__device__ int   g_is64;

// edge index load that works for int32 or int64 buffers
__device__ __forceinline__ int eidx(const void* ei, int pos) {
    if (g_is64) return (int)((const long long*)ei)[pos];
    return ((const int*)ei)[pos];
}

// ---------------- dtype detection ----------------
__global__ void k_detect(const unsigned* __restrict__ w) {
    __shared__ int anynz;
    if (threadIdx.x == 0) anynz = 0;
    __syncthreads();
    unsigned v = 0;
    for (int i = 1 + 2 * threadIdx.x; i < 8192; i += 2 * blockDim.x) v |= w[i];
    if (v) anynz = 1;
    __syncthreads();
    if (threadIdx.x == 0) g_is64 = anynz ? 0 : 1;
}

// ---------------- adjacency build ----------------
__global__ void k_zeroA() {
    int i = blockIdx.x * blockDim.x + threadIdx.x;
    ((float4*)g_A)[i] = make_float4(0.f, 0.f, 0.f, 0.f);
}

__global__ void k_buildA(const void* __restrict__ ei) {
    int e = blockIdx.x * blockDim.x + threadIdx.x;
    if (e >= EE) return;
    int s = eidx(ei, e), d = eidx(ei, EE + e);
    atomicAdd(&g_A[s * NN + d], 1.0f);
}

__global__ void k_diag() {
    int i = blockIdx.x * blockDim.x + threadIdx.x;
    if (i < NN) g_A[i * NN + i] += 1.0f;
}

// ---------------- fp32 A -> bf16 Abf (direct) + ATbf (transposed), fused ----------------
__global__ void k_cvtT() {
    __shared__ float tile[32][33];
    const int tx = threadIdx.x, ty = threadIdx.y;
    const int bx = blockIdx.x * 32, by = blockIdx.y * 32;
    #pragma unroll
    for (int r = 0; r < 32; r += 8) {
        float v = g_A[(size_t)(by + ty + r) * NN + bx + tx];
        tile[ty + r][tx] = v;
        g_Abf[(size_t)(by + ty + r) * NN + bx + tx] = __float2bfloat16(v);
    }
    __syncthreads();
    #pragma unroll
    for (int r = 0; r < 32; r += 8)
        g_ATbf[(size_t)(bx + ty + r) * NN + by + tx] =
            __float2bfloat16(tile[tx][ty + r]);
}

// ---------------- STbf = (A2)^T + A^T  (bf16-exact small integers) ----------------
__global__ void k_T2ST() {
    __shared__ float tile[32][33];
    const int tx = threadIdx.x, ty = threadIdx.y;
    const int bx = blockIdx.x * 32, by = blockIdx.y * 32;
    #pragma unroll
    for (int r = 0; r < 32; r += 8)
        tile[ty + r][tx] = __bfloat162float(g_A2bf[(size_t)(by + ty + r) * NN + bx + tx]);
    __syncthreads();
    #pragma unroll
    for (int r = 0; r < 32; r += 8) {
        size_t o = (size_t)(bx + ty + r) * NN + by + tx;
        float s = tile[tx][ty + r] + __bfloat162float(g_ATbf[o]);
        g_STbf[o] = __float2bfloat16(s);
    }
}

// ================= HMMA bf16 GEMM (mma.sync m16n8k16) =================
// D[m][n] = sum_k Aop[m][k] * Bop[n][k], Aop/Bop row-major [2048 x 2048] bf16.
// MODE 0: write bf16 to Cout.
// MODE 1: accumulate fp32 into Cout.
// MODE 2: write bf16 to Cout AND g_R = g_A + acc + I   (fuses k_initR)
#define GKC    64                 // K elems per chunk
#define NCHUNK (NN / GKC)         // 32
#define SM_TILE 16384             // 128 rows x 128B
#define GEMM_SMEM (4 * SM_TILE)   // A0,A1,B0,B1

__device__ __forceinline__ uint32_t smem_u32(const void* p) {
    uint32_t a;
    asm("{ .reg .u64 t; cvta.to.shared.u64 t, %1; cvt.u32.u64 %0, t; }" : "=r"(a) : "l"(p));
    return a;
}

__device__ __forceinline__ void ldmx4(uint32_t addr, uint32_t& r0, uint32_t& r1,
                                      uint32_t& r2, uint32_t& r3) {
    asm volatile("ldmatrix.sync.aligned.m8n8.x4.shared.b16 {%0,%1,%2,%3}, [%4];"
                 : "=r"(r0), "=r"(r1), "=r"(r2), "=r"(r3) : "r"(addr));
}

__device__ __forceinline__ void mma16816(float* d, uint32_t a0, uint32_t a1,
                                         uint32_t a2, uint32_t a3,
                                         uint32_t b0, uint32_t b1) {
    asm volatile("mma.sync.aligned.m16n8k16.row.col.f32.bf16.bf16.f32 "
                 "{%0,%1,%2,%3}, {%4,%5,%6,%7}, {%8,%9}, {%0,%1,%2,%3};"
                 : "+f"(d[0]), "+f"(d[1]), "+f"(d[2]), "+f"(d[3])
                 : "r"(a0), "r"(a1), "r"(a2), "r"(a3), "r"(b0), "r"(b1));
}

template<int MODE>
__global__ __launch_bounds__(256, 1)
void gemm_bf16mma(const __nv_bfloat16* __restrict__ Aop,
                  const __nv_bfloat16* __restrict__ Bop,
                  void* __restrict__ Cout)
{
    extern __shared__ __align__(1024) char smem[];
    const uint32_t sbase = smem_u32(smem);
    const int tid  = threadIdx.x;
    const int lane = tid & 31;
    const int w    = tid >> 5;
    const int wm   = w & 3;          // 0..3 (M)
    const int wn   = w >> 2;         // 0..1 (N)
    const int bm = blockIdx.y * 128, bn = blockIdx.x * 128;

    // ---- global load slots: 4 x 16B per tile per thread ----
    const __nv_bfloat16* aptr[4];
    const __nv_bfloat16* bptr[4];
    uint32_t soff[4];
    #pragma unroll
    for (int i = 0; i < 4; i++) {
        int q = tid + 256 * i;
        int row = q >> 3, seg = q & 7;
        aptr[i] = Aop + (size_t)(bm + row) * NN + seg * 8;
        bptr[i] = Bop + (size_t)(bn + row) * NN + seg * 8;
        soff[i] = row * 128 + (((row & 7) << 4) ^ (seg * 16));   // swizzled
    }

    // ---- ldmatrix address components ----
    const int a_r  = lane & 15;
    const int a_hi = lane >> 4;
    const int a_xor = (a_r & 7) << 4;
    const int arow0 = wm * 32 + a_r;
    const int b_g = lane >> 3, b_w = lane & 7;
    const int b_xor = b_w << 4;
    const int brow_base = wn * 64 + ((b_g >> 1) << 3) + b_w;
    const int b_khi = (b_g & 1) * 16;

    float acc[2][8][4];
    #pragma unroll
    for (int i = 0; i < 2; i++)
        #pragma unroll
        for (int j = 0; j < 8; j++)
            #pragma unroll
            for (int t = 0; t < 4; t++) acc[i][j][t] = 0.f;

    // ---- prologue: load + store chunk 0 ----
    uint4 va[4], vb[4];
    #pragma unroll
    for (int i = 0; i < 4; i++) { va[i] = *(const uint4*)aptr[i]; aptr[i] += GKC; }
    #pragma unroll
    for (int i = 0; i < 4; i++) { vb[i] = *(const uint4*)bptr[i]; bptr[i] += GKC; }
    #pragma unroll
    for (int i = 0; i < 4; i++)
        asm volatile("st.shared.v4.b32 [%0], {%1,%2,%3,%4};"
                     :: "r"(sbase + soff[i]), "r"(va[i].x), "r"(va[i].y), "r"(va[i].z), "r"(va[i].w) : "memory");
    #pragma unroll
    for (int i = 0; i < 4; i++)
        asm volatile("st.shared.v4.b32 [%0], {%1,%2,%3,%4};"
                     :: "r"(sbase + 2 * SM_TILE + soff[i]), "r"(vb[i].x), "r"(vb[i].y), "r"(vb[i].z), "r"(vb[i].w) : "memory");
    __syncthreads();

    for (int c = 0; c < NCHUNK; c++) {
        const int buf = c & 1;
        const uint32_t sA = sbase + buf * SM_TILE;
        const uint32_t sB = sbase + 2 * SM_TILE + buf * SM_TILE;

        if (c + 1 < NCHUNK) {
            #pragma unroll
            for (int i = 0; i < 4; i++) { va[i] = *(const uint4*)aptr[i]; aptr[i] += GKC; }
            #pragma unroll
            for (int i = 0; i < 4; i++) { vb[i] = *(const uint4*)bptr[i]; bptr[i] += GKC; }
        }

        #pragma unroll
        for (int ks = 0; ks < 4; ks++) {
            uint32_t a[2][4];
            #pragma unroll
            for (int im = 0; im < 2; im++) {
                int row = arow0 + im * 16;
                uint32_t addr = sA + row * 128 + (a_xor ^ (ks * 32 + a_hi * 16));
                ldmx4(addr, a[im][0], a[im][1], a[im][2], a[im][3]);
            }
            uint32_t b[8][2];
            #pragma unroll
            for (int jn = 0; jn < 4; jn++) {
                int row = brow_base + jn * 16;
                uint32_t addr = sB + row * 128 + (b_xor ^ (ks * 32 + b_khi));
                uint32_t r0, r1, r2, r3;
                ldmx4(addr, r0, r1, r2, r3);
                b[2 * jn][0] = r0; b[2 * jn][1] = r1;
                b[2 * jn + 1][0] = r2; b[2 * jn + 1][1] = r3;
            }
            #pragma unroll
            for (int im = 0; im < 2; im++)
                #pragma unroll
                for (int jf = 0; jf < 8; jf++)
                    mma16816(acc[im][jf], a[im][0], a[im][1], a[im][2], a[im][3],
                             b[jf][0], b[jf][1]);
        }

        if (c + 1 < NCHUNK) {
            const uint32_t dA = sbase + (buf ^ 1) * SM_TILE;
            const uint32_t dB = sbase + 2 * SM_TILE + (buf ^ 1) * SM_TILE;
            #pragma unroll
            for (int i = 0; i < 4; i++)
                asm volatile("st.shared.v4.b32 [%0], {%1,%2,%3,%4};"
                             :: "r"(dA + soff[i]), "r"(va[i].x), "r"(va[i].y), "r"(va[i].z), "r"(va[i].w) : "memory");
            #pragma unroll
            for (int i = 0; i < 4; i++)
                asm volatile("st.shared.v4.b32 [%0], {%1,%2,%3,%4};"
                             :: "r"(dB + soff[i]), "r"(vb[i].x), "r"(vb[i].y), "r"(vb[i].z), "r"(vb[i].w) : "memory");
        }
        __syncthreads();
    }

    // ---- epilogue ----
    const int mrow = bm + wm * 32 + (lane >> 2);
    const int ncol = bn + wn * 64 + 2 * (lane & 3);
    #pragma unroll
    for (int im = 0; im < 2; im++) {
        #pragma unroll
        for (int half = 0; half < 2; half++) {
            int m = mrow + im * 16 + half * 8;
            #pragma unroll
            for (int jf = 0; jf < 8; jf++) {
                int n = ncol + jf * 8;
                float v0 = acc[im][jf][2 * half];
                float v1 = acc[im][jf][2 * half + 1];
                if (MODE == 0 || MODE == 2) {
                    __nv_bfloat162 h = __float22bfloat162_rn(make_float2(v0, v1));
                    *(__nv_bfloat162*)((__nv_bfloat16*)Cout + (size_t)m * NN + n) = h;
                }
                if (MODE == 2) {
                    float2 av = *(const float2*)&g_A[(size_t)m * NN + n];
                    float r0 = av.x + v0 + (m == n       ? 1.0f : 0.0f);
                    float r1 = av.y + v1 + (m == (n + 1) ? 1.0f : 0.0f);
                    *(float2*)&g_R[(size_t)m * NN + n] = make_float2(r0, r1);
                }
                if (MODE == 1) {
                    float2* cp = (float2*)((float*)Cout + (size_t)m * NN + n);
                    float2 cv = *cp;
                    cv.x += v0; cv.y += v1;
                    *cp = cv;
                }
            }
        }
    }
}

// ---------------- fp32 SIMT GEMM (small lin layers): C = A*B^T ----------------
template<bool BT, int MODE>
__global__ __launch_bounds__(256, 2)
void gemm_f32(const float* __restrict__ A, const float* __restrict__ B,
              float* __restrict__ C, const float* __restrict__ bias,
              int M, int N, int K)
{
    __shared__ float As[BK][BM];
    __shared__ float Bs[BK][BN];
    const int tid = threadIdx.x;
    const int bm = blockIdx.y * BM;
    const int bn = blockIdx.x * BN;
    const int tx = tid & 15;
    const int ty = tid >> 4;
    const int aRow = tid >> 1;
    const int aCol = (tid & 1) * 4;

    float acc[8][8];
    #pragma unroll
    for (int i = 0; i < 8; i++)
        #pragma unroll
        for (int j = 0; j < 8; j++) acc[i][j] = 0.f;

    for (int k0 = 0; k0 < K; k0 += BK) {
        float4 av = *(const float4*)&A[(size_t)(bm + aRow) * K + k0 + aCol];
        As[aCol + 0][aRow] = av.x;
        As[aCol + 1][aRow] = av.y;
        As[aCol + 2][aRow] = av.z;
        As[aCol + 3][aRow] = av.w;
        if (BT) {
            float4 bv = *(const float4*)&B[(size_t)(bn + aRow) * K + k0 + aCol];
            Bs[aCol + 0][aRow] = bv.x;
            Bs[aCol + 1][aRow] = bv.y;
            Bs[aCol + 2][aRow] = bv.z;
            Bs[aCol + 3][aRow] = bv.w;
        } else {
            int bRow = tid >> 5;
            int bCol = (tid & 31) * 4;
            float4 bv = *(const float4*)&B[(size_t)(k0 + bRow) * N + bn + bCol];
            *(float4*)&Bs[bRow][bCol] = bv;
        }
        __syncthreads();

        #pragma unroll
        for (int k = 0; k < BK; k++) {
            float4 a0 = *(const float4*)&As[k][ty * 8];
            float4 a1 = *(const float4*)&As[k][ty * 8 + 4];
            float4 b0 = *(const float4*)&Bs[k][tx * 8];
            float4 b1 = *(const float4*)&Bs[k][tx * 8 + 4];
            float ra[8] = {a0.x, a0.y, a0.z, a0.w, a1.x, a1.y, a1.z, a1.w};
            float rb[8] = {b0.x, b0.y, b0.z, b0.w, b1.x, b1.y, b1.z, b1.w};
            #pragma unroll
            for (int i = 0; i < 8; i++)
                #pragma unroll
                for (int j = 0; j < 8; j++)
                    acc[i][j] += ra[i] * rb[j];
        }
        __syncthreads();
    }

    #pragma unroll
    for (int i = 0; i < 8; i++) {
        int row = bm + ty * 8 + i;
        float* cp = &C[(size_t)row * N + bn + tx * 8];
        if (MODE == 0) {
            *(float4*)&cp[0] = make_float4(acc[i][0], acc[i][1], acc[i][2], acc[i][3]);
            *(float4*)&cp[4] = make_float4(acc[i][4], acc[i][5], acc[i][6], acc[i][7]);
        } else {
            const float* bp = &bias[bn + tx * 8];
            *(float4*)&cp[0] = make_float4(acc[i][0] + bp[0], acc[i][1] + bp[1],
                                           acc[i][2] + bp[2], acc[i][3] + bp[3]);
            *(float4*)&cp[4] = make_float4(acc[i][4] + bp[4], acc[i][5] + bp[5],
                                           acc[i][6] + bp[6], acc[i][7] + bp[7]);
        }
    }
}

// ---------------- mask norm + per-edge mask value ----------------
__global__ void k_rownorm() {
    int r = blockIdx.x;
    __shared__ float sm[256];
    float s = 0.f;
    for (int c = threadIdx.x; c < NN; c += 256) {
        float v = g_R[(size_t)r * NN + c];
        s += v * v;
    }
    sm[threadIdx.x] = s;
    __syncthreads();
    for (int o = 128; o > 0; o >>= 1) {
        if (threadIdx.x < o) sm[threadIdx.x] += sm[threadIdx.x + o];
        __syncthreads();
    }
    if (threadIdx.x == 0) g_norm[r] = sqrtf(sm[0]);
}

__global__ void k_maskval(const void* __restrict__ ei) {
    int e = blockIdx.x * blockDim.x + threadIdx.x;
    if (e >= EE) return;
    int s = eidx(ei, e), d = eidx(ei, EE + e);
    float nrm = fmaxf(g_norm[s], 1e-12f);
    g_mv[e] = g_R[(size_t)s * NN + d] / nrm;
}

// ---------------- CSR by dst (counting sort) ----------------
__global__ void k_zerocnt() {
    int i = blockIdx.x * blockDim.x + threadIdx.x;
    if (i < NN) { g_cnt[i] = 0; g_cur[i] = 0; }
}

__global__ void k_count(const void* __restrict__ ei) {
    int e = blockIdx.x * blockDim.x + threadIdx.x;
    if (e >= EE) return;
    atomicAdd(&g_cnt[eidx(ei, EE + e)], 1);
}

// parallel exclusive scan of 2048 ints, 1024 threads (2 per thread)
__global__ void k_scan() {
    __shared__ int wsum[32];
    const int t = threadIdx.x;
    const int lane = t & 31, wid = t >> 5;
    int a = g_cnt[2 * t], b = g_cnt[2 * t + 1];
    int p = a + b;
    int v = p;
    #pragma unroll
    for (int o = 1; o < 32; o <<= 1) {
        int n = __shfl_up_sync(0xffffffffu, v, o);
        if (lane >= o) v += n;
    }
    if (lane == 31) wsum[wid] = v;
    __syncthreads();
    if (wid == 0) {
        int wv = wsum[lane];
        #pragma unroll
        for (int o = 1; o < 32; o <<= 1) {
            int n = __shfl_up_sync(0xffffffffu, wv, o);
            if (lane >= o) wv += n;
        }
        wsum[lane] = wv;
    }
    __syncthreads();
    int base = (wid > 0 ? wsum[wid - 1] : 0) + (v - p);   // exclusive prefix
    g_off[2 * t]     = base;
    g_off[2 * t + 1] = base + a;
    if (t == 1023) g_off[NN] = base + a + b;
}

__global__ void k_scatter(const void* __restrict__ ei) {
    int e = blockIdx.x * blockDim.x + threadIdx.x;
    if (e >= EE) return;
    int s = eidx(ei, e), d = eidx(ei, EE + e);
    int pos = g_off[d] + atomicAdd(&g_cur[d], 1);
    g_ssrc[pos] = s;
    g_seid[pos] = e;
}

// ---------------- attention ----------------
__global__ void k_s(const float* __restrict__ att) {
    int n = blockIdx.x;
    int w = threadIdx.x >> 5;
    int lane = threadIdx.x & 31;
    const float* row = g_xh + (size_t)n * (HH * CC) + w * CC;
    const float* ai = att + w * (2 * CC);
    const float* aj = ai + CC;
    float vi = 0.f, vj = 0.f;
    #pragma unroll
    for (int c = lane; c < CC; c += 32) {
        float v = row[c];
        vi += v * ai[c];
        vj += v * aj[c];
    }
    #pragma unroll
    for (int o = 16; o > 0; o >>= 1) {
        vi += __shfl_xor_sync(0xffffffffu, vi, o);
        vj += __shfl_xor_sync(0xffffffffu, vj, o);
    }
    if (lane == 0) { g_si[n * HH + w] = vi; g_sj[n * HH + w] = vj; }
}

__global__ void k_z(const void* __restrict__ ei) {
    int e = blockIdx.x * blockDim.x + threadIdx.x;
    if (e >= EE) return;
    int s = eidx(ei, e), d = eidx(ei, EE + e);
    float mv = g_mv[e];
    #pragma unroll
    for (int h = 0; h < HH; h++) {
        float a = g_si[d * HH + h] + g_sj[s * HH + h];
        a = (a >= 0.f) ? a : NEG * a;
        g_z[h * EE + e] = a * mv;
    }
}

// fused per-head softmax: max pass + exp/sum pass (z -> exp(z-m) in place)
__global__ void k_softmax() {
    const int h = blockIdx.x;
    float* zp = g_z + (size_t)h * EE;
    __shared__ float sm[1024];
    float m = -1e30f;
    for (int e = threadIdx.x; e < EE; e += 1024) m = fmaxf(m, zp[e]);
    sm[threadIdx.x] = m;
    __syncthreads();
    for (int o = 512; o > 0; o >>= 1) {
        if (threadIdx.x < o) sm[threadIdx.x] = fmaxf(sm[threadIdx.x], sm[threadIdx.x + o]);
        __syncthreads();
    }
    m = sm[0];
    __syncthreads();
    float s = 0.f;
    for (int e = threadIdx.x; e < EE; e += 1024) {
        float ex = expf(zp[e] - m);
        zp[e] = ex;
        s += ex;
    }
    sm[threadIdx.x] = s;
    __syncthreads();
    for (int o = 512; o > 0; o >>= 1) {
        if (threadIdx.x < o) sm[threadIdx.x] += sm[threadIdx.x + o];
        __syncthreads();
    }
    if (threadIdx.x == 0) g_Zs[h] = sm[0];
}

__global__ void k_aggregate(float* __restrict__ out) {
    int d = blockIdx.x;
    int c = threadIdx.x;
    int s0 = g_off[d], s1 = g_off[d + 1];
    float acc = 0.f;
    #pragma unroll
    for (int h = 0; h < HH; h++) {
        float a = 0.f;
        float invZ = 1.0f / g_Zs[h];
        for (int idx = s0; idx < s1; idx++) {
            int s = g_ssrc[idx];
            int e = g_seid[idx];
            a += g_z[h * EE + e] * g_xh[(size_t)s * (HH * CC) + h * CC + c];
        }
        acc += a * invZ;
    }
    acc *= (1.0f / HH);
    out[d * CC + c] = fmaxf(acc, 0.f);
}

__global__ void k_final(float* __restrict__ out) {
    int i = blockIdx.x * blockDim.x + threadIdx.x;
    out[i] = g_h2[i] + g_xskip[i];
}

// ---------------- launch ----------------
extern "C" void kernel_launch(void* const* d_in, const int* in_sizes, int n_in,
                              void* d_out, int out_size) {
    const float* x      = (const float*)d_in[0];
    const void*  ei     = d_in[1];
    const float* lin_w0 = (const float*)d_in[2];
    const float* att0   = (const float*)d_in[3];
    const float* lin_w1 = (const float*)d_in[4];
    const float* att1   = (const float*)d_in[5];
    const float* skip_w = (const float*)d_in[6];
    const float* skip_b = (const float*)d_in[7];
    float* out = (float*)d_out;

    void *pAbf, *pATbf, *pA2bf, *pSTbf, *pR;
    float *pXh, *pH1, *pH2, *pXs;
    cudaGetSymbolAddress(&pAbf,  g_Abf);
    cudaGetSymbolAddress(&pATbf, g_ATbf);
    cudaGetSymbolAddress(&pA2bf, g_A2bf);
    cudaGetSymbolAddress(&pSTbf, g_STbf);
    cudaGetSymbolAddress(&pR,    g_R);
    cudaGetSymbolAddress((void**)&pXh, g_xh);
    cudaGetSymbolAddress((void**)&pH1, g_h1);
    cudaGetSymbolAddress((void**)&pH2, g_h2);
    cudaGetSymbolAddress((void**)&pXs, g_xskip);

    cudaFuncSetAttribute(gemm_bf16mma<1>, cudaFuncAttributeMaxDynamicSharedMemorySize, GEMM_SMEM);
    cudaFuncSetAttribute(gemm_bf16mma<2>, cudaFuncAttributeMaxDynamicSharedMemorySize, GEMM_SMEM);

    k_detect<<<1, 256>>>((const unsigned*)ei);

    // build A' = adj + I (fp32), then bf16 copies A, A^T (fused)
    k_zeroA<<<(NN * NN / 4) / 256, 256>>>();
    k_buildA<<<EE / 256, 256>>>(ei);
    k_diag<<<NN / 256, 256>>>();
    k_cvtT<<<dim3(NN / 32, NN / 32), dim3(32, 8)>>>();

    // GEMM1 (MODE 2): A2 = A*A (bf16 out) AND R = A + A2 + I (fp32)
    dim3 gt(NN / 128, NN / 128);
    gemm_bf16mma<2><<<gt, 256, GEMM_SMEM>>>((const __nv_bfloat16*)pAbf,
                                            (const __nv_bfloat16*)pATbf, pA2bf);

    // ST = (A + A2)^T via transpose-of-A2 + add A^T (replaces 2nd big GEMM)
    k_T2ST<<<dim3(NN / 32, NN / 32), dim3(32, 8)>>>();

    // GEMM3 (MODE 1): R += A2 * (A + A2)   -> R = I+A+A2+A3+A4
    gemm_bf16mma<1><<<gt, 256, GEMM_SMEM>>>((const __nv_bfloat16*)pA2bf,
                                            (const __nv_bfloat16*)pSTbf, pR);

    k_rownorm<<<NN, 256>>>();
    k_maskval<<<EE / 256, 256>>>(ei);

    // CSR by dst
    k_zerocnt<<<NN / 256, 256>>>();
    k_count<<<EE / 256, 256>>>(ei);
    k_scan<<<1, 1024>>>();
    k_scatter<<<EE / 256, 256>>>(ei);

    // ---- layer 1 ----
    gemm_f32<true, 0><<<dim3((HH * CC) / BN, NN / BM), 256>>>(x, lin_w0, pXh, nullptr, NN, HH * CC, CC);
    k_s<<<NN, 256>>>(att0);
    k_z<<<EE / 256, 256>>>(ei);
    k_softmax<<<HH, 1024>>>();
    k_aggregate<<<NN, CC>>>(pH1);

    // ---- layer 2 ----
    gemm_f32<true, 0><<<dim3((HH * CC) / BN, NN / BM), 256>>>(pH1, lin_w1, pXh, nullptr, NN, HH * CC, CC);
    k_s<<<NN, 256>>>(att1);
    k_z<<<EE / 256, 256>>>(ei);
    k_softmax<<<HH, 1024>>>();
    k_aggregate<<<NN, CC>>>(pH2);

    // skip + final
    gemm_f32<true, 1><<<dim3(CC / BN, NN / BM), 256>>>(x, skip_w, pXs, skip_b, NN, CC, CC);
    k_final<<<(NN * CC) / 256, 256>>>(out);
}

// round 5
// speedup vs baseline: 4.7411x; 1.2339x over previous
#include <cuda_runtime.h>
#include <cuda_bf16.h>
#include <cstdint>
#include <math.h>

#define NN 2048
#define EE 65536
#define HH 8
#define CC 128
#define NEG 0.2f

#define BM 128
#define BN 128
#define BK 8

// ---------------- device scratch (static: no allocations allowed) ----------------
__device__ float          g_A [NN*NN];     // fp32 raw adjacency counts (NO diag)
__device__ float          g_R [NN*NN];     // fp32 mask accumulator
__device__ __nv_bfloat16  g_Abf  [NN*NN];  // bf16 A' = A + I
__device__ __nv_bfloat16  g_ATbf [NN*NN];  // bf16 A'^T
__device__ __nv_bfloat16  g_A2bf [NN*NN];  // bf16 A'^2
__device__ __nv_bfloat16  g_STbf [NN*NN];  // (A' + A'^2)^T in bf16
__device__ float g_xh[NN*HH*CC];
__device__ float g_si[NN*HH];
__device__ float g_sj[NN*HH];
__device__ float g_z [HH*EE];
__device__ float g_mv[EE];
__device__ float g_Zs[HH];
__device__ float g_norm[NN];
__device__ int   g_cnt[NN];
__device__ int   g_cur[NN];
__device__ int   g_off[NN+1];
__device__ int   g_ssrc[EE];
__device__ int   g_seid[EE];
__device__ float g_h1[NN*CC];
__device__ float g_h2[NN*CC];
__device__ float g_xskip[NN*CC];
__device__ int   g_is64;

// edge index load that works for int32 or int64 buffers
__device__ __forceinline__ int eidx(const void* ei, int pos) {
    if (g_is64) return (int)((const long long*)ei)[pos];
    return ((const int*)ei)[pos];
}

// ---------------- dtype detection ----------------
__global__ void k_detect(const unsigned* __restrict__ w) {
    __shared__ int anynz;
    if (threadIdx.x == 0) anynz = 0;
    __syncthreads();
    unsigned v = 0;
    for (int i = 1 + 2 * threadIdx.x; i < 8192; i += 2 * blockDim.x) v |= w[i];
    if (v) anynz = 1;
    __syncthreads();
    if (threadIdx.x == 0) g_is64 = anynz ? 0 : 1;
}

// ---------------- adjacency build ----------------
__global__ void k_zeroA() {
    int i = blockIdx.x * blockDim.x + threadIdx.x;
    ((float4*)g_A)[i] = make_float4(0.f, 0.f, 0.f, 0.f);
}

__global__ void k_buildA(const void* __restrict__ ei) {
    int e = blockIdx.x * blockDim.x + threadIdx.x;
    if (e >= EE) return;
    int s = eidx(ei, e), d = eidx(ei, EE + e);
    atomicAdd(&g_A[s * NN + d], 1.0f);
}

// ---------------- fp32 A -> bf16 A' (adds +I) + A'^T, fused ----------------
__global__ void k_cvtT() {
    __shared__ float tile[32][33];
    const int tx = threadIdx.x, ty = threadIdx.y;
    const int bx = blockIdx.x * 32, by = blockIdx.y * 32;
    #pragma unroll
    for (int r = 0; r < 32; r += 8) {
        int row = by + ty + r, col = bx + tx;
        float v = g_A[(size_t)row * NN + col];
        tile[ty + r][tx] = v;
        g_Abf[(size_t)row * NN + col] = __float2bfloat16(v + (row == col ? 1.0f : 0.0f));
    }
    __syncthreads();
    #pragma unroll
    for (int r = 0; r < 32; r += 8) {
        int trow = bx + ty + r, tcol = by + tx;   // ATbf[trow][tcol] = A'[tcol][trow]
        float v = tile[tx][ty + r] + (trow == tcol ? 1.0f : 0.0f);
        g_ATbf[(size_t)trow * NN + tcol] = __float2bfloat16(v);
    }
}

// ---------------- STbf = (A2)^T + A'^T  (bf16-exact small integers) ----------------
__global__ void k_T2ST() {
    __shared__ float tile[32][33];
    const int tx = threadIdx.x, ty = threadIdx.y;
    const int bx = blockIdx.x * 32, by = blockIdx.y * 32;
    #pragma unroll
    for (int r = 0; r < 32; r += 8)
        tile[ty + r][tx] = __bfloat162float(g_A2bf[(size_t)(by + ty + r) * NN + bx + tx]);
    __syncthreads();
    #pragma unroll
    for (int r = 0; r < 32; r += 8) {
        size_t o = (size_t)(bx + ty + r) * NN + by + tx;
        float s = tile[tx][ty + r] + __bfloat162float(g_ATbf[o]);
        g_STbf[o] = __float2bfloat16(s);
    }
}

// ================= HMMA bf16 GEMM (mma.sync m16n8k16, cp.async pipeline) =========
// D[m][n] = sum_k Aop[m][k] * Bop[n][k], Aop/Bop row-major [2048 x 2048] bf16.
// MODE 1: accumulate fp32 into Cout.
// MODE 2: write bf16 to Cout AND g_R = g_A + acc + 2I  (fuses k_initR; g_A has no diag)
#define GKC    64                 // K elems per chunk
#define NCHUNK (NN / GKC)         // 32
#define SM_TILE 16384             // 128 rows x 128B
#define GEMM_SMEM (4 * SM_TILE)   // A0,A1,B0,B1

__device__ __forceinline__ uint32_t smem_u32(const void* p) {
    uint32_t a;
    asm("{ .reg .u64 t; cvta.to.shared.u64 t, %1; cvt.u32.u64 %0, t; }" : "=r"(a) : "l"(p));
    return a;
}

__device__ __forceinline__ void cp16(uint32_t saddr, const void* gaddr) {
    asm volatile("cp.async.cg.shared.global [%0], [%1], 16;" :: "r"(saddr), "l"(gaddr));
}

__device__ __forceinline__ void ldmx4(uint32_t addr, uint32_t& r0, uint32_t& r1,
                                      uint32_t& r2, uint32_t& r3) {
    asm volatile("ldmatrix.sync.aligned.m8n8.x4.shared.b16 {%0,%1,%2,%3}, [%4];"
                 : "=r"(r0), "=r"(r1), "=r"(r2), "=r"(r3) : "r"(addr));
}

__device__ __forceinline__ void mma16816(float* d, uint32_t a0, uint32_t a1,
                                         uint32_t a2, uint32_t a3,
                                         uint32_t b0, uint32_t b1) {
    asm volatile("mma.sync.aligned.m16n8k16.row.col.f32.bf16.bf16.f32 "
                 "{%0,%1,%2,%3}, {%4,%5,%6,%7}, {%8,%9}, {%0,%1,%2,%3};"
                 : "+f"(d[0]), "+f"(d[1]), "+f"(d[2]), "+f"(d[3])
                 : "r"(a0), "r"(a1), "r"(a2), "r"(a3), "r"(b0), "r"(b1));
}

template<int MODE>
__global__ __launch_bounds__(256, 2)
void gemm_bf16mma(const __nv_bfloat16* __restrict__ Aop,
                  const __nv_bfloat16* __restrict__ Bop,
                  void* __restrict__ Cout)
{
    extern __shared__ __align__(1024) char smem[];
    const uint32_t sbase = smem_u32(smem);
    const int tid  = threadIdx.x;
    const int lane = tid & 31;
    const int w    = tid >> 5;
    const int wm   = w & 3;          // 0..3 (M)
    const int wn   = w >> 2;         // 0..1 (N)
    const int bm = blockIdx.y * 128, bn = blockIdx.x * 128;

    // ---- cp.async slots: slot i handles row (tid>>3)+32*i, 16B seg (tid&7) ----
    const int row0 = tid >> 3, seg = tid & 7;
    const __nv_bfloat16* abase = Aop + (size_t)(bm + row0) * NN + seg * 8;
    const __nv_bfloat16* bbase = Bop + (size_t)(bn + row0) * NN + seg * 8;
    const uint32_t soff0 = row0 * 128 + (((row0 & 7) << 4) ^ (seg * 16));  // swizzled

    // ---- ldmatrix address components ----
    const int a_r  = lane & 15;
    const int a_hi = lane >> 4;
    const int a_xor = (a_r & 7) << 4;
    const int arow0 = wm * 32 + a_r;
    const int b_g = lane >> 3, b_w = lane & 7;
    const int b_xor = b_w << 4;
    const int brow_base = wn * 64 + ((b_g >> 1) << 3) + b_w;
    const int b_khi = (b_g & 1) * 16;

    float acc[2][8][4];
    #pragma unroll
    for (int i = 0; i < 2; i++)
        #pragma unroll
        for (int j = 0; j < 8; j++)
            #pragma unroll
            for (int t = 0; t < 4; t++) acc[i][j][t] = 0.f;

    // ---- issue chunk 0 ----
    {
        const uint32_t dA = sbase, dB = sbase + 2 * SM_TILE;
        #pragma unroll
        for (int i = 0; i < 4; i++)
            cp16(dA + soff0 + i * 4096, abase + (size_t)(32 * i) * NN);
        #pragma unroll
        for (int i = 0; i < 4; i++)
            cp16(dB + soff0 + i * 4096, bbase + (size_t)(32 * i) * NN);
        asm volatile("cp.async.commit_group;");
    }

    for (int c = 0; c < NCHUNK; c++) {
        asm volatile("cp.async.wait_group 0;");
        __syncthreads();

        if (c + 1 < NCHUNK) {
            const int nb = (c + 1) & 1;
            const uint32_t dA = sbase + nb * SM_TILE;
            const uint32_t dB = sbase + 2 * SM_TILE + nb * SM_TILE;
            const __nv_bfloat16* ap = abase + (c + 1) * GKC;
            const __nv_bfloat16* bp = bbase + (c + 1) * GKC;
            #pragma unroll
            for (int i = 0; i < 4; i++)
                cp16(dA + soff0 + i * 4096, ap + (size_t)(32 * i) * NN);
            #pragma unroll
            for (int i = 0; i < 4; i++)
                cp16(dB + soff0 + i * 4096, bp + (size_t)(32 * i) * NN);
            asm volatile("cp.async.commit_group;");
        }

        const int buf = c & 1;
        const uint32_t sA = sbase + buf * SM_TILE;
        const uint32_t sB = sbase + 2 * SM_TILE + buf * SM_TILE;

        #pragma unroll
        for (int ks = 0; ks < 4; ks++) {
            uint32_t a[2][4];
            #pragma unroll
            for (int im = 0; im < 2; im++) {
                int row = arow0 + im * 16;
                uint32_t addr = sA + row * 128 + (a_xor ^ (ks * 32 + a_hi * 16));
                ldmx4(addr, a[im][0], a[im][1], a[im][2], a[im][3]);
            }
            #pragma unroll
            for (int jn = 0; jn < 4; jn++) {
                int row = brow_base + jn * 16;
                uint32_t addr = sB + row * 128 + (b_xor ^ (ks * 32 + b_khi));
                uint32_t r0, r1, r2, r3;
                ldmx4(addr, r0, r1, r2, r3);
                mma16816(acc[0][2 * jn],     a[0][0], a[0][1], a[0][2], a[0][3], r0, r1);
                mma16816(acc[0][2 * jn + 1], a[0][0], a[0][1], a[0][2], a[0][3], r2, r3);
                mma16816(acc[1][2 * jn],     a[1][0], a[1][1], a[1][2], a[1][3], r0, r1);
                mma16816(acc[1][2 * jn + 1], a[1][0], a[1][1], a[1][2], a[1][3], r2, r3);
            }
        }
    }

    // ---- epilogue ----
    const int mrow = bm + wm * 32 + (lane >> 2);
    const int ncol = bn + wn * 64 + 2 * (lane & 3);
    #pragma unroll
    for (int im = 0; im < 2; im++) {
        #pragma unroll
        for (int half = 0; half < 2; half++) {
            int m = mrow + im * 16 + half * 8;
            #pragma unroll
            for (int jf = 0; jf < 8; jf++) {
                int n = ncol + jf * 8;
                float v0 = acc[im][jf][2 * half];
                float v1 = acc[im][jf][2 * half + 1];
                if (MODE == 2) {
                    __nv_bfloat162 h = __float22bfloat162_rn(make_float2(v0, v1));
                    *(__nv_bfloat162*)((__nv_bfloat16*)Cout + (size_t)m * NN + n) = h;
                    float2 av = *(const float2*)&g_A[(size_t)m * NN + n];
                    float r0 = av.x + v0 + (m == n       ? 2.0f : 0.0f);
                    float r1 = av.y + v1 + (m == (n + 1) ? 2.0f : 0.0f);
                    *(float2*)&g_R[(size_t)m * NN + n] = make_float2(r0, r1);
                }
                if (MODE == 1) {
                    float2* cp = (float2*)((float*)Cout + (size_t)m * NN + n);
                    float2 cv = *cp;
                    cv.x += v0; cv.y += v1;
                    *cp = cv;
                }
            }
        }
    }
}

// ---------------- fp32 SIMT GEMM (small lin layers): C = A*B^T ----------------
template<bool BT, int MODE>
__global__ __launch_bounds__(256, 2)
void gemm_f32(const float* __restrict__ A, const float* __restrict__ B,
              float* __restrict__ C, const float* __restrict__ bias,
              int M, int N, int K)
{
    __shared__ float As[BK][BM];
    __shared__ float Bs[BK][BN];
    const int tid = threadIdx.x;
    const int bm = blockIdx.y * BM;
    const int bn = blockIdx.x * BN;
    const int tx = tid & 15;
    const int ty = tid >> 4;
    const int aRow = tid >> 1;
    const int aCol = (tid & 1) * 4;

    float acc[8][8];
    #pragma unroll
    for (int i = 0; i < 8; i++)
        #pragma unroll
        for (int j = 0; j < 8; j++) acc[i][j] = 0.f;

    for (int k0 = 0; k0 < K; k0 += BK) {
        float4 av = *(const float4*)&A[(size_t)(bm + aRow) * K + k0 + aCol];
        As[aCol + 0][aRow] = av.x;
        As[aCol + 1][aRow] = av.y;
        As[aCol + 2][aRow] = av.z;
        As[aCol + 3][aRow] = av.w;
        if (BT) {
            float4 bv = *(const float4*)&B[(size_t)(bn + aRow) * K + k0 + aCol];
            Bs[aCol + 0][aRow] = bv.x;
            Bs[aCol + 1][aRow] = bv.y;
            Bs[aCol + 2][aRow] = bv.z;
            Bs[aCol + 3][aRow] = bv.w;
        } else {
            int bRow = tid >> 5;
            int bCol = (tid & 31) * 4;
            float4 bv = *(const float4*)&B[(size_t)(k0 + bRow) * N + bn + bCol];
            *(float4*)&Bs[bRow][bCol] = bv;
        }
        __syncthreads();

        #pragma unroll
        for (int k = 0; k < BK; k++) {
            float4 a0 = *(const float4*)&As[k][ty * 8];
            float4 a1 = *(const float4*)&As[k][ty * 8 + 4];
            float4 b0 = *(const float4*)&Bs[k][tx * 8];
            float4 b1 = *(const float4*)&Bs[k][tx * 8 + 4];
            float ra[8] = {a0.x, a0.y, a0.z, a0.w, a1.x, a1.y, a1.z, a1.w};
            float rb[8] = {b0.x, b0.y, b0.z, b0.w, b1.x, b1.y, b1.z, b1.w};
            #pragma unroll
            for (int i = 0; i < 8; i++)
                #pragma unroll
                for (int j = 0; j < 8; j++)
                    acc[i][j] += ra[i] * rb[j];
        }
        __syncthreads();
    }

    #pragma unroll
    for (int i = 0; i < 8; i++) {
        int row = bm + ty * 8 + i;
        float* cp = &C[(size_t)row * N + bn + tx * 8];
        if (MODE == 0) {
            *(float4*)&cp[0] = make_float4(acc[i][0], acc[i][1], acc[i][2], acc[i][3]);
            *(float4*)&cp[4] = make_float4(acc[i][4], acc[i][5], acc[i][6], acc[i][7]);
        } else {
            const float* bp = &bias[bn + tx * 8];
            *(float4*)&cp[0] = make_float4(acc[i][0] + bp[0], acc[i][1] + bp[1],
                                           acc[i][2] + bp[2], acc[i][3] + bp[3]);
            *(float4*)&cp[4] = make_float4(acc[i][4] + bp[4], acc[i][5] + bp[5],
                                           acc[i][6] + bp[6], acc[i][7] + bp[7]);
        }
    }
}

// ---------------- mask norm + per-edge mask value ----------------
__global__ void k_rownorm() {
    int r = blockIdx.x;
    __shared__ float sm[256];
    float s = 0.f;
    for (int c = threadIdx.x; c < NN; c += 256) {
        float v = g_R[(size_t)r * NN + c];
        s += v * v;
    }
    sm[threadIdx.x] = s;
    __syncthreads();
    for (int o = 128; o > 0; o >>= 1) {
        if (threadIdx.x < o) sm[threadIdx.x] += sm[threadIdx.x + o];
        __syncthreads();
    }
    if (threadIdx.x == 0) g_norm[r] = sqrtf(sm[0]);
}

__global__ void k_maskval(const void* __restrict__ ei) {
    int e = blockIdx.x * blockDim.x + threadIdx.x;
    if (e >= EE) return;
    int s = eidx(ei, e), d = eidx(ei, EE + e);
    float nrm = fmaxf(g_norm[s], 1e-12f);
    g_mv[e] = g_R[(size_t)s * NN + d] / nrm;
}

// ---------------- CSR by dst (counting sort) ----------------
__global__ void k_zerocnt() {
    int i = blockIdx.x * blockDim.x + threadIdx.x;
    if (i < NN) { g_cnt[i] = 0; g_cur[i] = 0; }
}

__global__ void k_count(const void* __restrict__ ei) {
    int e = blockIdx.x * blockDim.x + threadIdx.x;
    if (e >= EE) return;
    atomicAdd(&g_cnt[eidx(ei, EE + e)], 1);
}

// parallel exclusive scan of 2048 ints, 1024 threads (2 per thread)
__global__ void k_scan() {
    __shared__ int wsum[32];
    const int t = threadIdx.x;
    const int lane = t & 31, wid = t >> 5;
    int a = g_cnt[2 * t], b = g_cnt[2 * t + 1];
    int p = a + b;
    int v = p;
    #pragma unroll
    for (int o = 1; o < 32; o <<= 1) {
        int n = __shfl_up_sync(0xffffffffu, v, o);
        if (lane >= o) v += n;
    }
    if (lane == 31) wsum[wid] = v;
    __syncthreads();
    if (wid == 0) {
        int wv = wsum[lane];
        #pragma unroll
        for (int o = 1; o < 32; o <<= 1) {
            int n = __shfl_up_sync(0xffffffffu, wv, o);
            if (lane >= o) wv += n;
        }
        wsum[lane] = wv;
    }
    __syncthreads();
    int base = (wid > 0 ? wsum[wid - 1] : 0) + (v - p);   // exclusive prefix
    g_off[2 * t]     = base;
    g_off[2 * t + 1] = base + a;
    if (t == 1023) g_off[NN] = base + a + b;
}

__global__ void k_scatter(const void* __restrict__ ei) {
    int e = blockIdx.x * blockDim.x + threadIdx.x;
    if (e >= EE) return;
    int s = eidx(ei, e), d = eidx(ei, EE + e);
    int pos = g_off[d] + atomicAdd(&g_cur[d], 1);
    g_ssrc[pos] = s;
    g_seid[pos] = e;
}

// ---------------- attention ----------------
__global__ void k_s(const float* __restrict__ att) {
    int n = blockIdx.x;
    int w = threadIdx.x >> 5;
    int lane = threadIdx.x & 31;
    const float* row = g_xh + (size_t)n * (HH * CC) + w * CC;
    const float* ai = att + w * (2 * CC);
    const float* aj = ai + CC;
    float vi = 0.f, vj = 0.f;
    #pragma unroll
    for (int c = lane; c < CC; c += 32) {
        float v = row[c];
        vi += v * ai[c];
        vj += v * aj[c];
    }
    #pragma unroll
    for (int o = 16; o > 0; o >>= 1) {
        vi += __shfl_xor_sync(0xffffffffu, vi, o);
        vj += __shfl_xor_sync(0xffffffffu, vj, o);
    }
    if (lane == 0) { g_si[n * HH + w] = vi; g_sj[n * HH + w] = vj; }
}

__global__ void k_z(const void* __restrict__ ei) {
    int e = blockIdx.x * blockDim.x + threadIdx.x;
    if (e >= EE) return;
    int s = eidx(ei, e), d = eidx(ei, EE + e);
    float mv = g_mv[e];
    #pragma unroll
    for (int h = 0; h < HH; h++) {
        float a = g_si[d * HH + h] + g_sj[s * HH + h];
        a = (a >= 0.f) ? a : NEG * a;
        g_z[h * EE + e] = a * mv;
    }
}

// fused per-head softmax: max pass + exp/sum pass (z -> exp(z-m) in place)
__global__ void k_softmax() {
    const int h = blockIdx.x;
    float* zp = g_z + (size_t)h * EE;
    __shared__ float sm[1024];
    float m = -1e30f;
    for (int e = threadIdx.x; e < EE; e += 1024) m = fmaxf(m, zp[e]);
    sm[threadIdx.x] = m;
    __syncthreads();
    for (int o = 512; o > 0; o >>= 1) {
        if (threadIdx.x < o) sm[threadIdx.x] = fmaxf(sm[threadIdx.x], sm[threadIdx.x + o]);
        __syncthreads();
    }
    m = sm[0];
    __syncthreads();
    float s = 0.f;
    for (int e = threadIdx.x; e < EE; e += 1024) {
        float ex = expf(zp[e] - m);
        zp[e] = ex;
        s += ex;
    }
    sm[threadIdx.x] = s;
    __syncthreads();
    for (int o = 512; o > 0; o >>= 1) {
        if (threadIdx.x < o) sm[threadIdx.x] += sm[threadIdx.x + o];
        __syncthreads();
    }
    if (threadIdx.x == 0) g_Zs[h] = sm[0];
}

__global__ void k_aggregate(float* __restrict__ out) {
    int d = blockIdx.x;
    int c = threadIdx.x;
    int s0 = g_off[d], s1 = g_off[d + 1];
    float acc = 0.f;
    #pragma unroll
    for (int h = 0; h < HH; h++) {
        float a = 0.f;
        float invZ = 1.0f / g_Zs[h];
        for (int idx = s0; idx < s1; idx++) {
            int s = g_ssrc[idx];
            int e = g_seid[idx];
            a += g_z[h * EE + e] * g_xh[(size_t)s * (HH * CC) + h * CC + c];
        }
        acc += a * invZ;
    }
    acc *= (1.0f / HH);
    out[d * CC + c] = fmaxf(acc, 0.f);
}

__global__ void k_final(float* __restrict__ out) {
    int i = blockIdx.x * blockDim.x + threadIdx.x;
    out[i] = g_h2[i] + g_xskip[i];
}

// ---------------- launch ----------------
extern "C" void kernel_launch(void* const* d_in, const int* in_sizes, int n_in,
                              void* d_out, int out_size) {
    const float* x      = (const float*)d_in[0];
    const void*  ei     = d_in[1];
    const float* lin_w0 = (const float*)d_in[2];
    const float* att0   = (const float*)d_in[3];
    const float* lin_w1 = (const float*)d_in[4];
    const float* att1   = (const float*)d_in[5];
    const float* skip_w = (const float*)d_in[6];
    const float* skip_b = (const float*)d_in[7];
    float* out = (float*)d_out;

    void *pAbf, *pATbf, *pA2bf, *pSTbf, *pR;
    float *pXh, *pH1, *pH2, *pXs;
    cudaGetSymbolAddress(&pAbf,  g_Abf);
    cudaGetSymbolAddress(&pATbf, g_ATbf);
    cudaGetSymbolAddress(&pA2bf, g_A2bf);
    cudaGetSymbolAddress(&pSTbf, g_STbf);
    cudaGetSymbolAddress(&pR,    g_R);
    cudaGetSymbolAddress((void**)&pXh, g_xh);
    cudaGetSymbolAddress((void**)&pH1, g_h1);
    cudaGetSymbolAddress((void**)&pH2, g_h2);
    cudaGetSymbolAddress((void**)&pXs, g_xskip);

    cudaFuncSetAttribute(gemm_bf16mma<1>, cudaFuncAttributeMaxDynamicSharedMemorySize, GEMM_SMEM);
    cudaFuncSetAttribute(gemm_bf16mma<2>, cudaFuncAttributeMaxDynamicSharedMemorySize, GEMM_SMEM);

    // fork-join: side stream for the lin/CSR track (created per call; not freed
    // during capture — a handful of calls total, no device memory involved)
    cudaStream_t s1;
    cudaEvent_t ev0, ev1;
    cudaStreamCreateWithFlags(&s1, cudaStreamNonBlocking);
    cudaEventCreateWithFlags(&ev0, cudaEventDisableTiming);
    cudaEventCreateWithFlags(&ev1, cudaEventDisableTiming);

    k_detect<<<1, 256>>>((const unsigned*)ei);
    cudaEventRecord(ev0, 0);
    cudaStreamWaitEvent(s1, ev0, 0);

    // ---- side track (s1): CSR + layer-1 lin + attention scores + skip ----
    k_zerocnt<<<NN / 256, 256, 0, s1>>>();
    k_count<<<EE / 256, 256, 0, s1>>>(ei);
    k_scan<<<1, 1024, 0, s1>>>();
    k_scatter<<<EE / 256, 256, 0, s1>>>(ei);
    gemm_f32<true, 0><<<dim3((HH * CC) / BN, NN / BM), 256, 0, s1>>>(x, lin_w0, pXh, nullptr, NN, HH * CC, CC);
    k_s<<<NN, 256, 0, s1>>>(att0);
    gemm_f32<true, 1><<<dim3(CC / BN, NN / BM), 256, 0, s1>>>(x, skip_w, pXs, skip_b, NN, CC, CC);
    cudaEventRecord(ev1, s1);

    // ---- main track: mask chain ----
    k_zeroA<<<(NN * NN / 4) / 256, 256>>>();
    k_buildA<<<EE / 256, 256>>>(ei);
    k_cvtT<<<dim3(NN / 32, NN / 32), dim3(32, 8)>>>();

    dim3 gt(NN / 128, NN / 128);
    // GEMM1 (MODE 2): A2 = A'*A' (bf16) AND R = rawA + A2 + 2I (= A' + A2 + I)
    gemm_bf16mma<2><<<gt, 256, GEMM_SMEM>>>((const __nv_bfloat16*)pAbf,
                                            (const __nv_bfloat16*)pATbf, pA2bf);
    // ST = (A' + A2)^T via transpose + add
    k_T2ST<<<dim3(NN / 32, NN / 32), dim3(32, 8)>>>();
    // GEMM2 (MODE 1): R += A2 * (A' + A2)   -> R = I+A'+A2+A3+A4
    gemm_bf16mma<1><<<gt, 256, GEMM_SMEM>>>((const __nv_bfloat16*)pA2bf,
                                            (const __nv_bfloat16*)pSTbf, pR);
    k_rownorm<<<NN, 256>>>();
    k_maskval<<<EE / 256, 256>>>(ei);

    // join
    cudaStreamWaitEvent(0, ev1, 0);

    // ---- layer 1 attention ----
    k_z<<<EE / 256, 256>>>(ei);
    k_softmax<<<HH, 1024>>>();
    k_aggregate<<<NN, CC>>>(pH1);

    // ---- layer 2 ----
    gemm_f32<true, 0><<<dim3((HH * CC) / BN, NN / BM), 256>>>(pH1, lin_w1, pXh, nullptr, NN, HH * CC, CC);
    k_s<<<NN, 256>>>(att1);
    k_z<<<EE / 256, 256>>>(ei);
    k_softmax<<<HH, 1024>>>();
    k_aggregate<<<NN, CC>>>(pH2);

    k_final<<<(NN * CC) / 256, 256>>>(out);
}

// round 6
// speedup vs baseline: 5.3398x; 1.1263x over previous
#include <cuda_runtime.h>
#include <cuda_bf16.h>
#include <cstdint>
#include <math.h>

#define NN 2048
#define EE 65536
#define HH 8
#define CC 128
#define NEG 0.2f

#define BM 128
#define BN 128
#define BK 8

// ---------------- device scratch (static: no allocations allowed) ----------------
__device__ float          g_A  [NN*NN];    // fp32 raw adjacency counts (NO diag)
__device__ float          g_A2f[NN*NN];    // fp32 A^2 raw (path counts), then unused
__device__ float          g_R  [NN*NN];    // fp32 mask accumulator
__device__ __nv_bfloat16  g_A2bf[NN*NN];   // bf16 A'^2
__device__ __nv_bfloat16  g_STbf[NN*NN];   // (A' + A'^2)^T in bf16
__device__ float g_xh[NN*HH*CC];
__device__ float g_si[NN*HH];
__device__ float g_sj[NN*HH];
__device__ float g_z [HH*EE];
__device__ float g_mv[EE];
__device__ float g_Zs[HH];
__device__ float g_norm[NN];
__device__ int   g_cnt[NN];
__device__ int   g_cur[NN];
__device__ int   g_off[NN+1];
__device__ int   g_ssrc[EE];
__device__ int   g_seid[EE];
__device__ float g_h1[NN*CC];
__device__ float g_h2[NN*CC];
__device__ float g_xskip[NN*CC];
__device__ int   g_is64;

// edge index load that works for int32 or int64 buffers
__device__ __forceinline__ int eidx(const void* ei, int pos) {
    if (g_is64) return (int)((const long long*)ei)[pos];
    return ((const int*)ei)[pos];
}

// ---------------- dtype detection ----------------
__global__ void k_detect(const unsigned* __restrict__ w) {
    __shared__ int anynz;
    if (threadIdx.x == 0) anynz = 0;
    __syncthreads();
    unsigned v = 0;
    for (int i = 1 + 2 * threadIdx.x; i < 8192; i += 2 * blockDim.x) v |= w[i];
    if (v) anynz = 1;
    __syncthreads();
    if (threadIdx.x == 0) g_is64 = anynz ? 0 : 1;
}

// ---------------- zero A and A2f ----------------
__global__ void k_zero2() {
    int i = blockIdx.x * blockDim.x + threadIdx.x;   // 2*NN*NN/4 float4s
    const int half = (NN * NN) / 4;
    float4 z = make_float4(0.f, 0.f, 0.f, 0.f);
    if (i < half) ((float4*)g_A)[i] = z;
    else          ((float4*)g_A2f)[i - half] = z;
}

__global__ void k_buildA(const void* __restrict__ ei) {
    int e = blockIdx.x * blockDim.x + threadIdx.x;
    if (e >= EE) return;
    int s = eidx(ei, e), d = eidx(ei, EE + e);
    atomicAdd(&g_A[s * NN + d], 1.0f);
}

// ---------------- sparse A^2 build: for edge (k->j), +1 for each in-edge (i->k) ----
__global__ void k_buildA2(const void* __restrict__ ei) {
    int e = blockIdx.x * blockDim.x + threadIdx.x;
    if (e >= EE) return;
    int k = eidx(ei, e), j = eidx(ei, EE + e);
    int s0 = g_off[k], s1 = g_off[k + 1];
    for (int idx = s0; idx < s1; idx++) {
        int i = g_ssrc[idx];
        atomicAdd(&g_A2f[(size_t)i * NN + j], 1.0f);
    }
}

// ---------------- fused prep: A2' = A2raw + 2A + I ; S = A' + A2' ; R = S + I ;
//                  A2bf = bf16(A2') ; STbf = bf16(S)^T  ---------------------------
__global__ void k_prep() {
    __shared__ float tile[32][33];
    const int tx = threadIdx.x, ty = threadIdx.y;
    const int bx = blockIdx.x * 32, by = blockIdx.y * 32;
    #pragma unroll
    for (int r = 0; r < 32; r += 8) {
        int row = by + ty + r, col = bx + tx;
        size_t o = (size_t)row * NN + col;
        float a = g_A[o];
        float b = g_A2f[o];
        float diag = (row == col) ? 1.0f : 0.0f;
        float a2 = b + 2.0f * a + diag;       // A'^2
        float S  = a + a2 + diag;             // A' + A'^2
        g_R[o] = S + diag;                    // I + A' + A'^2
        g_A2bf[o] = __float2bfloat16(a2);
        tile[ty + r][tx] = S;
    }
    __syncthreads();
    #pragma unroll
    for (int r = 0; r < 32; r += 8)
        g_STbf[(size_t)(bx + ty + r) * NN + by + tx] =
            __float2bfloat16(tile[tx][ty + r]);
}

// ================= HMMA bf16 GEMM (mma.sync m16n8k16, cp.async pipeline) =========
// Cout(fp32) += sum_k Aop[m][k] * Bop[n][k], row-major [2048 x 2048] bf16.
#define GKC    64                 // K elems per chunk
#define NCHUNK (NN / GKC)         // 32
#define SM_TILE 16384             // 128 rows x 128B
#define GEMM_SMEM (4 * SM_TILE)   // A0,A1,B0,B1

__device__ __forceinline__ uint32_t smem_u32(const void* p) {
    uint32_t a;
    asm("{ .reg .u64 t; cvta.to.shared.u64 t, %1; cvt.u32.u64 %0, t; }" : "=r"(a) : "l"(p));
    return a;
}

__device__ __forceinline__ void cp16(uint32_t saddr, const void* gaddr) {
    asm volatile("cp.async.cg.shared.global [%0], [%1], 16;" :: "r"(saddr), "l"(gaddr));
}

__device__ __forceinline__ void ldmx4(uint32_t addr, uint32_t& r0, uint32_t& r1,
                                      uint32_t& r2, uint32_t& r3) {
    asm volatile("ldmatrix.sync.aligned.m8n8.x4.shared.b16 {%0,%1,%2,%3}, [%4];"
                 : "=r"(r0), "=r"(r1), "=r"(r2), "=r"(r3) : "r"(addr));
}

__device__ __forceinline__ void mma16816(float* d, uint32_t a0, uint32_t a1,
                                         uint32_t a2, uint32_t a3,
                                         uint32_t b0, uint32_t b1) {
    asm volatile("mma.sync.aligned.m16n8k16.row.col.f32.bf16.bf16.f32 "
                 "{%0,%1,%2,%3}, {%4,%5,%6,%7}, {%8,%9}, {%0,%1,%2,%3};"
                 : "+f"(d[0]), "+f"(d[1]), "+f"(d[2]), "+f"(d[3])
                 : "r"(a0), "r"(a1), "r"(a2), "r"(a3), "r"(b0), "r"(b1));
}

__global__ __launch_bounds__(256, 2)
void gemm_bf16mma(const __nv_bfloat16* __restrict__ Aop,
                  const __nv_bfloat16* __restrict__ Bop,
                  float* __restrict__ Cout)
{
    extern __shared__ __align__(1024) char smem[];
    const uint32_t sbase = smem_u32(smem);
    const int tid  = threadIdx.x;
    const int lane = tid & 31;
    const int w    = tid >> 5;
    const int wm   = w & 3;          // 0..3 (M)
    const int wn   = w >> 2;         // 0..1 (N)
    const int bm = blockIdx.y * 128, bn = blockIdx.x * 128;

    const int row0 = tid >> 3, seg = tid & 7;
    const __nv_bfloat16* abase = Aop + (size_t)(bm + row0) * NN + seg * 8;
    const __nv_bfloat16* bbase = Bop + (size_t)(bn + row0) * NN + seg * 8;
    const uint32_t soff0 = row0 * 128 + (((row0 & 7) << 4) ^ (seg * 16));  // swizzled

    const int a_r  = lane & 15;
    const int a_hi = lane >> 4;
    const int a_xor = (a_r & 7) << 4;
    const int arow0 = wm * 32 + a_r;
    const int b_g = lane >> 3, b_w = lane & 7;
    const int b_xor = b_w << 4;
    const int brow_base = wn * 64 + ((b_g >> 1) << 3) + b_w;
    const int b_khi = (b_g & 1) * 16;

    float acc[2][8][4];
    #pragma unroll
    for (int i = 0; i < 2; i++)
        #pragma unroll
        for (int j = 0; j < 8; j++)
            #pragma unroll
            for (int t = 0; t < 4; t++) acc[i][j][t] = 0.f;

    {
        const uint32_t dA = sbase, dB = sbase + 2 * SM_TILE;
        #pragma unroll
        for (int i = 0; i < 4; i++)
            cp16(dA + soff0 + i * 4096, abase + (size_t)(32 * i) * NN);
        #pragma unroll
        for (int i = 0; i < 4; i++)
            cp16(dB + soff0 + i * 4096, bbase + (size_t)(32 * i) * NN);
        asm volatile("cp.async.commit_group;");
    }

    for (int c = 0; c < NCHUNK; c++) {
        asm volatile("cp.async.wait_group 0;");
        __syncthreads();

        if (c + 1 < NCHUNK) {
            const int nb = (c + 1) & 1;
            const uint32_t dA = sbase + nb * SM_TILE;
            const uint32_t dB = sbase + 2 * SM_TILE + nb * SM_TILE;
            const __nv_bfloat16* ap = abase + (c + 1) * GKC;
            const __nv_bfloat16* bp = bbase + (c + 1) * GKC;
            #pragma unroll
            for (int i = 0; i < 4; i++)
                cp16(dA + soff0 + i * 4096, ap + (size_t)(32 * i) * NN);
            #pragma unroll
            for (int i = 0; i < 4; i++)
                cp16(dB + soff0 + i * 4096, bp + (size_t)(32 * i) * NN);
            asm volatile("cp.async.commit_group;");
        }

        const int buf = c & 1;
        const uint32_t sA = sbase + buf * SM_TILE;
        const uint32_t sB = sbase + 2 * SM_TILE + buf * SM_TILE;

        #pragma unroll
        for (int ks = 0; ks < 4; ks++) {
            uint32_t a[2][4];
            #pragma unroll
            for (int im = 0; im < 2; im++) {
                int row = arow0 + im * 16;
                uint32_t addr = sA + row * 128 + (a_xor ^ (ks * 32 + a_hi * 16));
                ldmx4(addr, a[im][0], a[im][1], a[im][2], a[im][3]);
            }
            #pragma unroll
            for (int jn = 0; jn < 4; jn++) {
                int row = brow_base + jn * 16;
                uint32_t addr = sB + row * 128 + (b_xor ^ (ks * 32 + b_khi));
                uint32_t r0, r1, r2, r3;
                ldmx4(addr, r0, r1, r2, r3);
                mma16816(acc[0][2 * jn],     a[0][0], a[0][1], a[0][2], a[0][3], r0, r1);
                mma16816(acc[0][2 * jn + 1], a[0][0], a[0][1], a[0][2], a[0][3], r2, r3);
                mma16816(acc[1][2 * jn],     a[1][0], a[1][1], a[1][2], a[1][3], r0, r1);
                mma16816(acc[1][2 * jn + 1], a[1][0], a[1][1], a[1][2], a[1][3], r2, r3);
            }
        }
    }

    const int mrow = bm + wm * 32 + (lane >> 2);
    const int ncol = bn + wn * 64 + 2 * (lane & 3);
    #pragma unroll
    for (int im = 0; im < 2; im++) {
        #pragma unroll
        for (int half = 0; half < 2; half++) {
            int m = mrow + im * 16 + half * 8;
            #pragma unroll
            for (int jf = 0; jf < 8; jf++) {
                int n = ncol + jf * 8;
                float2* cp = (float2*)&Cout[(size_t)m * NN + n];
                float2 cv = *cp;
                cv.x += acc[im][jf][2 * half];
                cv.y += acc[im][jf][2 * half + 1];
                *cp = cv;
            }
        }
    }
}

// ---------------- fp32 SIMT GEMM (small lin layers): C = A*B^T ----------------
template<bool BT, int MODE>
__global__ __launch_bounds__(256, 2)
void gemm_f32(const float* __restrict__ A, const float* __restrict__ B,
              float* __restrict__ C, const float* __restrict__ bias,
              int M, int N, int K)
{
    __shared__ float As[BK][BM];
    __shared__ float Bs[BK][BN];
    const int tid = threadIdx.x;
    const int bm = blockIdx.y * BM;
    const int bn = blockIdx.x * BN;
    const int tx = tid & 15;
    const int ty = tid >> 4;
    const int aRow = tid >> 1;
    const int aCol = (tid & 1) * 4;

    float acc[8][8];
    #pragma unroll
    for (int i = 0; i < 8; i++)
        #pragma unroll
        for (int j = 0; j < 8; j++) acc[i][j] = 0.f;

    for (int k0 = 0; k0 < K; k0 += BK) {
        float4 av = *(const float4*)&A[(size_t)(bm + aRow) * K + k0 + aCol];
        As[aCol + 0][aRow] = av.x;
        As[aCol + 1][aRow] = av.y;
        As[aCol + 2][aRow] = av.z;
        As[aCol + 3][aRow] = av.w;
        if (BT) {
            float4 bv = *(const float4*)&B[(size_t)(bn + aRow) * K + k0 + aCol];
            Bs[aCol + 0][aRow] = bv.x;
            Bs[aCol + 1][aRow] = bv.y;
            Bs[aCol + 2][aRow] = bv.z;
            Bs[aCol + 3][aRow] = bv.w;
        } else {
            int bRow = tid >> 5;
            int bCol = (tid & 31) * 4;
            float4 bv = *(const float4*)&B[(size_t)(k0 + bRow) * N + bn + bCol];
            *(float4*)&Bs[bRow][bCol] = bv;
        }
        __syncthreads();

        #pragma unroll
        for (int k = 0; k < BK; k++) {
            float4 a0 = *(const float4*)&As[k][ty * 8];
            float4 a1 = *(const float4*)&As[k][ty * 8 + 4];
            float4 b0 = *(const float4*)&Bs[k][tx * 8];
            float4 b1 = *(const float4*)&Bs[k][tx * 8 + 4];
            float ra[8] = {a0.x, a0.y, a0.z, a0.w, a1.x, a1.y, a1.z, a1.w};
            float rb[8] = {b0.x, b0.y, b0.z, b0.w, b1.x, b1.y, b1.z, b1.w};
            #pragma unroll
            for (int i = 0; i < 8; i++)
                #pragma unroll
                for (int j = 0; j < 8; j++)
                    acc[i][j] += ra[i] * rb[j];
        }
        __syncthreads();
    }

    #pragma unroll
    for (int i = 0; i < 8; i++) {
        int row = bm + ty * 8 + i;
        float* cp = &C[(size_t)row * N + bn + tx * 8];
        if (MODE == 0) {
            *(float4*)&cp[0] = make_float4(acc[i][0], acc[i][1], acc[i][2], acc[i][3]);
            *(float4*)&cp[4] = make_float4(acc[i][4], acc[i][5], acc[i][6], acc[i][7]);
        } else {
            const float* bp = &bias[bn + tx * 8];
            *(float4*)&cp[0] = make_float4(acc[i][0] + bp[0], acc[i][1] + bp[1],
                                           acc[i][2] + bp[2], acc[i][3] + bp[3]);
            *(float4*)&cp[4] = make_float4(acc[i][4] + bp[4], acc[i][5] + bp[5],
                                           acc[i][6] + bp[6], acc[i][7] + bp[7]);
        }
    }
}

// ---------------- mask norm + per-edge mask value ----------------
__global__ void k_rownorm() {
    int r = blockIdx.x;
    __shared__ float sm[256];
    float s = 0.f;
    for (int c = threadIdx.x; c < NN; c += 256) {
        float v = g_R[(size_t)r * NN + c];
        s += v * v;
    }
    sm[threadIdx.x] = s;
    __syncthreads();
    for (int o = 128; o > 0; o >>= 1) {
        if (threadIdx.x < o) sm[threadIdx.x] += sm[threadIdx.x + o];
        __syncthreads();
    }
    if (threadIdx.x == 0) g_norm[r] = sqrtf(sm[0]);
}

__global__ void k_maskval(const void* __restrict__ ei) {
    int e = blockIdx.x * blockDim.x + threadIdx.x;
    if (e >= EE) return;
    int s = eidx(ei, e), d = eidx(ei, EE + e);
    float nrm = fmaxf(g_norm[s], 1e-12f);
    g_mv[e] = g_R[(size_t)s * NN + d] / nrm;
}

// ---------------- CSR by dst (counting sort) ----------------
__global__ void k_zerocnt() {
    int i = blockIdx.x * blockDim.x + threadIdx.x;
    if (i < NN) { g_cnt[i] = 0; g_cur[i] = 0; }
}

__global__ void k_count(const void* __restrict__ ei) {
    int e = blockIdx.x * blockDim.x + threadIdx.x;
    if (e >= EE) return;
    atomicAdd(&g_cnt[eidx(ei, EE + e)], 1);
}

// parallel exclusive scan of 2048 ints, 1024 threads (2 per thread)
__global__ void k_scan() {
    __shared__ int wsum[32];
    const int t = threadIdx.x;
    const int lane = t & 31, wid = t >> 5;
    int a = g_cnt[2 * t], b = g_cnt[2 * t + 1];
    int p = a + b;
    int v = p;
    #pragma unroll
    for (int o = 1; o < 32; o <<= 1) {
        int n = __shfl_up_sync(0xffffffffu, v, o);
        if (lane >= o) v += n;
    }
    if (lane == 31) wsum[wid] = v;
    __syncthreads();
    if (wid == 0) {
        int wv = wsum[lane];
        #pragma unroll
        for (int o = 1; o < 32; o <<= 1) {
            int n = __shfl_up_sync(0xffffffffu, wv, o);
            if (lane >= o) wv += n;
        }
        wsum[lane] = wv;
    }
    __syncthreads();
    int base = (wid > 0 ? wsum[wid - 1] : 0) + (v - p);   // exclusive prefix
    g_off[2 * t]     = base;
    g_off[2 * t + 1] = base + a;
    if (t == 1023) g_off[NN] = base + a + b;
}

__global__ void k_scatter(const void* __restrict__ ei) {
    int e = blockIdx.x * blockDim.x + threadIdx.x;
    if (e >= EE) return;
    int s = eidx(ei, e), d = eidx(ei, EE + e);
    int pos = g_off[d] + atomicAdd(&g_cur[d], 1);
    g_ssrc[pos] = s;
    g_seid[pos] = e;
}

// ---------------- attention ----------------
__global__ void k_s(const float* __restrict__ att) {
    int n = blockIdx.x;
    int w = threadIdx.x >> 5;
    int lane = threadIdx.x & 31;
    const float* row = g_xh + (size_t)n * (HH * CC) + w * CC;
    const float* ai = att + w * (2 * CC);
    const float* aj = ai + CC;
    float vi = 0.f, vj = 0.f;
    #pragma unroll
    for (int c = lane; c < CC; c += 32) {
        float v = row[c];
        vi += v * ai[c];
        vj += v * aj[c];
    }
    #pragma unroll
    for (int o = 16; o > 0; o >>= 1) {
        vi += __shfl_xor_sync(0xffffffffu, vi, o);
        vj += __shfl_xor_sync(0xffffffffu, vj, o);
    }
    if (lane == 0) { g_si[n * HH + w] = vi; g_sj[n * HH + w] = vj; }
}

__global__ void k_z(const void* __restrict__ ei) {
    int e = blockIdx.x * blockDim.x + threadIdx.x;
    if (e >= EE) return;
    int s = eidx(ei, e), d = eidx(ei, EE + e);
    float mv = g_mv[e];
    #pragma unroll
    for (int h = 0; h < HH; h++) {
        float a = g_si[d * HH + h] + g_sj[s * HH + h];
        a = (a >= 0.f) ? a : NEG * a;
        g_z[h * EE + e] = a * mv;
    }
}

// fused per-head softmax: max pass + exp/sum pass (z -> exp(z-m) in place)
__global__ void k_softmax() {
    const int h = blockIdx.x;
    float* zp = g_z + (size_t)h * EE;
    __shared__ float sm[1024];
    float m = -1e30f;
    for (int e = threadIdx.x; e < EE; e += 1024) m = fmaxf(m, zp[e]);
    sm[threadIdx.x] = m;
    __syncthreads();
    for (int o = 512; o > 0; o >>= 1) {
        if (threadIdx.x < o) sm[threadIdx.x] = fmaxf(sm[threadIdx.x], sm[threadIdx.x + o]);
        __syncthreads();
    }
    m = sm[0];
    __syncthreads();
    float s = 0.f;
    for (int e = threadIdx.x; e < EE; e += 1024) {
        float ex = expf(zp[e] - m);
        zp[e] = ex;
        s += ex;
    }
    sm[threadIdx.x] = s;
    __syncthreads();
    for (int o = 512; o > 0; o >>= 1) {
        if (threadIdx.x < o) sm[threadIdx.x] += sm[threadIdx.x + o];
        __syncthreads();
    }
    if (threadIdx.x == 0) g_Zs[h] = sm[0];
}

__global__ void k_aggregate(float* __restrict__ out) {
    int d = blockIdx.x;
    int c = threadIdx.x;
    int s0 = g_off[d], s1 = g_off[d + 1];
    float acc = 0.f;
    #pragma unroll
    for (int h = 0; h < HH; h++) {
        float a = 0.f;
        float invZ = 1.0f / g_Zs[h];
        for (int idx = s0; idx < s1; idx++) {
            int s = g_ssrc[idx];
            int e = g_seid[idx];
            a += g_z[h * EE + e] * g_xh[(size_t)s * (HH * CC) + h * CC + c];
        }
        acc += a * invZ;
    }
    acc *= (1.0f / HH);
    out[d * CC + c] = fmaxf(acc, 0.f);
}

__global__ void k_final(float* __restrict__ out) {
    int i = blockIdx.x * blockDim.x + threadIdx.x;
    out[i] = g_h2[i] + g_xskip[i];
}

// ---------------- launch ----------------
extern "C" void kernel_launch(void* const* d_in, const int* in_sizes, int n_in,
                              void* d_out, int out_size) {
    const float* x      = (const float*)d_in[0];
    const void*  ei     = d_in[1];
    const float* lin_w0 = (const float*)d_in[2];
    const float* att0   = (const float*)d_in[3];
    const float* lin_w1 = (const float*)d_in[4];
    const float* att1   = (const float*)d_in[5];
    const float* skip_w = (const float*)d_in[6];
    const float* skip_b = (const float*)d_in[7];
    float* out = (float*)d_out;

    void *pA2bf, *pSTbf;
    float *pR, *pXh, *pH1, *pH2, *pXs;
    cudaGetSymbolAddress(&pA2bf, g_A2bf);
    cudaGetSymbolAddress(&pSTbf, g_STbf);
    cudaGetSymbolAddress((void**)&pR,  g_R);
    cudaGetSymbolAddress((void**)&pXh, g_xh);
    cudaGetSymbolAddress((void**)&pH1, g_h1);
    cudaGetSymbolAddress((void**)&pH2, g_h2);
    cudaGetSymbolAddress((void**)&pXs, g_xskip);

    cudaFuncSetAttribute(gemm_bf16mma, cudaFuncAttributeMaxDynamicSharedMemorySize, GEMM_SMEM);

    // fork-join: side stream for the lin/skip track
    cudaStream_t s1;
    cudaEvent_t ev0, ev1;
    cudaStreamCreateWithFlags(&s1, cudaStreamNonBlocking);
    cudaEventCreateWithFlags(&ev0, cudaEventDisableTiming);
    cudaEventCreateWithFlags(&ev1, cudaEventDisableTiming);

    k_detect<<<1, 256>>>((const unsigned*)ei);
    cudaEventRecord(ev0, 0);
    cudaStreamWaitEvent(s1, ev0, 0);

    // ---- side track (s1): layer-1 lin + attention scores + skip ----
    gemm_f32<true, 0><<<dim3((HH * CC) / BN, NN / BM), 256, 0, s1>>>(x, lin_w0, pXh, nullptr, NN, HH * CC, CC);
    k_s<<<NN, 256, 0, s1>>>(att0);
    gemm_f32<true, 1><<<dim3(CC / BN, NN / BM), 256, 0, s1>>>(x, skip_w, pXs, skip_b, NN, CC, CC);
    cudaEventRecord(ev1, s1);

    // ---- main track: mask chain (sparse A^2 + one dense GEMM) ----
    k_zero2<<<(2 * NN * NN / 4) / 256, 256>>>();
    k_zerocnt<<<NN / 256, 256>>>();
    k_buildA<<<EE / 256, 256>>>(ei);
    k_count<<<EE / 256, 256>>>(ei);
    k_scan<<<1, 1024>>>();
    k_scatter<<<EE / 256, 256>>>(ei);
    k_buildA2<<<EE / 256, 256>>>(ei);
    k_prep<<<dim3(NN / 32, NN / 32), dim3(32, 8)>>>();

    // GEMM: R += A2' * (A' + A2')   -> R = I+A'+A2+A3+A4
    dim3 gt(NN / 128, NN / 128);
    gemm_bf16mma<<<gt, 256, GEMM_SMEM>>>((const __nv_bfloat16*)pA2bf,
                                         (const __nv_bfloat16*)pSTbf, pR);
    k_rownorm<<<NN, 256>>>();
    k_maskval<<<EE / 256, 256>>>(ei);

    // join
    cudaStreamWaitEvent(0, ev1, 0);

    // ---- layer 1 attention ----
    k_z<<<EE / 256, 256>>>(ei);
    k_softmax<<<HH, 1024>>>();
    k_aggregate<<<NN, CC>>>(pH1);

    // ---- layer 2 ----
    gemm_f32<true, 0><<<dim3((HH * CC) / BN, NN / BM), 256>>>(pH1, lin_w1, pXh, nullptr, NN, HH * CC, CC);
    k_s<<<NN, 256>>>(att1);
    k_z<<<EE / 256, 256>>>(ei);
    k_softmax<<<HH, 1024>>>();
    k_aggregate<<<NN, CC>>>(pH2);

    k_final<<<(NN * CC) / 256, 256>>>(out);
}